// round 2
// baseline (speedup 1.0000x reference)
#include <cuda_runtime.h>
#include <cuda_bf16.h>
#include <cuda_fp16.h>
#include <cuda_fp8.h>
#include <cstdint>

// Problem constants
#define TT 512
#define DD 2048
#define II 768
#define EE 16
#define KTOP 8

#define NW13_INT (EE*2*II*(DD/2))   // 16*1536*1024
#define NW2_INT  (EE*DD*(II/2))     // 16*2048*384

// ---------------- device scratch (no allocations allowed) ----------------
__device__ __nv_bfloat16 g_xq[TT*DD];                    // quant-dequant x (exact bf16)
__device__ __nv_bfloat16 g_w13b[(size_t)EE*2*II*DD];     // dequant w13 (exact bf16)
__device__ __half        g_w2h [(size_t)EE*DD*II];       // dequant w2 (exact fp16)
__device__ __half        g_act [(size_t)EE*TT*II];       // silu(g)*u  (fp16)
__device__ float g_comb[TT*EE];
__device__ int   g_cnt[EE];
__device__ int   g_tok[EE*TT];

// ---------------- helpers ----------------
__device__ __forceinline__ void ldm_x4(uint32_t r[4], const void* p) {
    uint32_t addr = (uint32_t)__cvta_generic_to_shared(p);
    asm volatile("ldmatrix.sync.aligned.m8n8.x4.shared.b16 {%0,%1,%2,%3}, [%4];"
                 : "=r"(r[0]), "=r"(r[1]), "=r"(r[2]), "=r"(r[3]) : "r"(addr));
}
__device__ __forceinline__ void mma_bf16(float c[4], const uint32_t a[4], uint32_t b0, uint32_t b1) {
    asm volatile("mma.sync.aligned.m16n8k16.row.col.f32.bf16.bf16.f32 "
                 "{%0,%1,%2,%3},{%4,%5,%6,%7},{%8,%9},{%0,%1,%2,%3};"
                 : "+f"(c[0]), "+f"(c[1]), "+f"(c[2]), "+f"(c[3])
                 : "r"(a[0]), "r"(a[1]), "r"(a[2]), "r"(a[3]), "r"(b0), "r"(b1));
}
__device__ __forceinline__ void mma_f16(float c[4], const uint32_t a[4], uint32_t b0, uint32_t b1) {
    asm volatile("mma.sync.aligned.m16n8k16.row.col.f32.f16.f16.f32 "
                 "{%0,%1,%2,%3},{%4,%5,%6,%7},{%8,%9},{%0,%1,%2,%3};"
                 : "+f"(c[0]), "+f"(c[1]), "+f"(c[2]), "+f"(c[3])
                 : "r"(a[0]), "r"(a[1]), "r"(a[2]), "r"(a[3]), "r"(b0), "r"(b1));
}

// fp4(e2m1) nibble -> bf16 bits, times 2^(sf-127) (eo = (sf-127)<<7), pure integer
__device__ __forceinline__ unsigned fp4_bf16(unsigned nib, int eo) {
    unsigned mag = nib & 7u;
    unsigned sgn = (nib & 8u) << 12;
    unsigned base = (mag >= 2u) ? (0x3F00u + (mag << 6)) : (mag * 0x3F00u);
    unsigned val = mag ? (unsigned)((int)base + eo) : 0u;
    return val | sgn;
}
// fp4 nibble -> fp16 bits, times 2^(sf-127) (eo = (sf-127)<<10)
__device__ __forceinline__ unsigned fp4_fp16(unsigned nib, int eo) {
    unsigned mag = nib & 7u;
    unsigned sgn = (nib & 8u) << 12;
    unsigned base = (mag >= 2u) ? (0x3800u + (mag << 9)) : (mag * 0x3800u);
    unsigned val = mag ? (unsigned)((int)base + eo) : 0u;
    return val | sgn;
}

// ---------------- kernel 1: zero out + counters ----------------
__global__ void k_zero(float* __restrict__ out) {
    int i = blockIdx.x * blockDim.x + threadIdx.x;
    if (i < TT*DD) out[i] = 0.f;
    if (i < EE) g_cnt[i] = 0;
}

// ---------------- kernel 2: fp8 quant-dequant of x (warp per group of 32) ----------------
__global__ void k_quant(const float* __restrict__ x) {
    int gid = blockIdx.x * blockDim.x + threadIdx.x;   // element index == group*32 + lane
    float v = x[gid];
    float a = fabsf(v);
    #pragma unroll
    for (int off = 16; off; off >>= 1) a = fmaxf(a, __shfl_xor_sync(0xFFFFFFFFu, a, off));
    a = fmaxf(a, 0.0001f);
    float scale = a * (1.0f / 448.0f);
    unsigned bits = __float_as_uint(scale);
    unsigned exp = ((bits >> 23) & 255u) + ((bits & 0x7FFFFFu) != 0u);
    exp = min(max(exp, 1u), 254u);
    float rscale = __uint_as_float(exp << 23);
    float inv = 1.0f / rscale;
    __nv_fp8_storage_t q = __nv_cvt_float_to_fp8(v * inv, __NV_SATFINITE, __NV_E4M3);
    float dq = __half2float(__half(__nv_cvt_fp8_to_halfraw(q, __NV_E4M3))) * rscale;
    g_xq[gid] = __float2bfloat16(dq);
}

// ---------------- kernel 3: pre-dequant fp4 weights ----------------
__global__ void k_dequant(const int* __restrict__ w13, const int* __restrict__ w13s,
                          const int* __restrict__ w2,  const int* __restrict__ w2s) {
    long id = (long)blockIdx.x * blockDim.x + threadIdx.x;
    if (id < NW13_INT) {
        long r = id >> 10;            // row among E*2I, 1024 ints per row
        long c = id & 1023;
        int sf = w13s[r * 64 + (c >> 4)];
        unsigned v = (unsigned)w13[id];
        int eo = (sf - 127) << 7;
        unsigned lo = fp4_bf16(v & 15u, eo);
        unsigned hi = fp4_bf16((v >> 4) & 15u, eo);
        *(unsigned*)((unsigned short*)g_w13b + r * 2048 + 2 * c) = lo | (hi << 16);
    } else if (id < (long)NW13_INT + NW2_INT) {
        long j = id - NW13_INT;
        long r = j / 384;             // row among E*D, 384 ints per row
        long c = j % 384;
        int sf = w2s[r * 24 + (c >> 4)];
        unsigned v = (unsigned)w2[j];
        int eo = (sf - 127) << 10;
        unsigned lo = fp4_fp16(v & 15u, eo);
        unsigned hi = fp4_fp16((v >> 4) & 15u, eo);
        *(unsigned*)((unsigned short*)g_w2h + r * 768 + 2 * c) = lo | (hi << 16);
    }
}

// ---------------- kernel 4: per-token combine weights ----------------
__global__ void k_route1(const float* __restrict__ tw, const int* __restrict__ tids) {
    int t = blockIdx.x * blockDim.x + threadIdx.x;
    if (t >= TT) return;
    float c[EE];
    #pragma unroll
    for (int e = 0; e < EE; e++) c[e] = 0.f;
    #pragma unroll
    for (int k = 0; k < KTOP; k++) c[tids[t*KTOP + k]] += tw[t*KTOP + k];
    #pragma unroll
    for (int e = 0; e < EE; e++) g_comb[t*EE + e] = c[e];
}

// ---------------- kernel 5: build per-expert token lists ----------------
__global__ void k_route2() {
    int id = blockIdx.x * blockDim.x + threadIdx.x;
    if (id >= TT*EE) return;
    int t = id >> 4, e = id & 15;
    if (g_comb[id] > 0.f) {
        int s = atomicAdd(&g_cnt[e], 1);
        g_tok[e*TT + s] = t;
    }
}

// ---------------- kernel 6: GEMM1 (x @ W13^T) + silu*up -> g_act ----------------
__global__ __launch_bounds__(128) void k_gemm1() {
    const int e = blockIdx.z;
    const int cnt = g_cnt[e];
    const int m0 = blockIdx.x * 64;
    if (m0 >= cnt) return;
    const int n0 = blockIdx.y * 64;   // [0, 768)

    __shared__ __nv_bfloat16 As[64][40];
    __shared__ __nv_bfloat16 Bg[64][40];
    __shared__ __nv_bfloat16 Bu[64][40];
    __shared__ int s_tok[64];

    const int tid = threadIdx.x;
    const int lane = tid & 31, warp = tid >> 5;
    const int wm = warp >> 1, wn = warp & 1;

    if (tid < 64) {
        int r = m0 + tid;
        s_tok[tid] = (r < cnt) ? g_tok[e*TT + r] : -1;
    }

    float accg[2][4][4], accu[2][4][4];
    #pragma unroll
    for (int a = 0; a < 2; a++)
        #pragma unroll
        for (int b = 0; b < 4; b++)
            #pragma unroll
            for (int c = 0; c < 4; c++) { accg[a][b][c] = 0.f; accu[a][b][c] = 0.f; }

    const __nv_bfloat16* w13g = g_w13b + (size_t)e*2*II*DD + (size_t)n0*DD;
    const __nv_bfloat16* w13u = w13g + (size_t)II*DD;

    __syncthreads();

    for (int kb = 0; kb < DD/32; ++kb) {
        const int k0 = kb * 32;
        #pragma unroll
        for (int l = 0; l < 2; ++l) {
            int idx = tid + l*128;
            int row = idx >> 2, seg = idx & 3;
            uint4 va = make_uint4(0,0,0,0);
            int t = s_tok[row];
            if (t >= 0) va = *(const uint4*)(g_xq + (size_t)t*DD + k0 + seg*8);
            *(uint4*)(&As[row][seg*8]) = va;
            *(uint4*)(&Bg[row][seg*8]) = *(const uint4*)(w13g + (size_t)row*DD + k0 + seg*8);
            *(uint4*)(&Bu[row][seg*8]) = *(const uint4*)(w13u + (size_t)row*DD + k0 + seg*8);
        }
        __syncthreads();

        #pragma unroll
        for (int kk = 0; kk < 32; kk += 16) {
            uint32_t a[2][4];
            #pragma unroll
            for (int mt = 0; mt < 2; ++mt)
                ldm_x4(a[mt], &As[wm*32 + mt*16 + (lane & 15)][kk + ((lane >> 4) << 3)]);
            uint32_t bg[4][2], bu[4][2];
            #pragma unroll
            for (int nh = 0; nh < 2; ++nh) {
                uint32_t t4[4];
                ldm_x4(t4, &Bg[wn*32 + nh*16 + (lane & 15)][kk + ((lane >> 4) << 3)]);
                bg[nh*2+0][0] = t4[0]; bg[nh*2+1][0] = t4[1];
                bg[nh*2+0][1] = t4[2]; bg[nh*2+1][1] = t4[3];
                ldm_x4(t4, &Bu[wn*32 + nh*16 + (lane & 15)][kk + ((lane >> 4) << 3)]);
                bu[nh*2+0][0] = t4[0]; bu[nh*2+1][0] = t4[1];
                bu[nh*2+0][1] = t4[2]; bu[nh*2+1][1] = t4[3];
            }
            #pragma unroll
            for (int mt = 0; mt < 2; ++mt)
                #pragma unroll
                for (int nc = 0; nc < 4; ++nc) {
                    mma_bf16(accg[mt][nc], a[mt], bg[nc][0], bg[nc][1]);
                    mma_bf16(accu[mt][nc], a[mt], bu[nc][0], bu[nc][1]);
                }
        }
        __syncthreads();
    }

    // epilogue: a = silu(gate) * up -> fp16 g_act (zero-A rows produce 0, safe to store)
    const size_t abase = ((size_t)e*TT + m0) * II + n0;
    #pragma unroll
    for (int mt = 0; mt < 2; ++mt)
        #pragma unroll
        for (int nc = 0; nc < 4; ++nc)
            #pragma unroll
            for (int rp = 0; rp < 2; ++rp) {
                int row = wm*32 + mt*16 + (lane >> 2) + rp*8;
                int col = wn*32 + nc*8 + ((lane & 3) << 1);
                float g0 = accg[mt][nc][rp*2+0], g1 = accg[mt][nc][rp*2+1];
                float u0 = accu[mt][nc][rp*2+0], u1 = accu[mt][nc][rp*2+1];
                float a0 = (g0 / (1.f + expf(-g0))) * u0;
                float a1 = (g1 / (1.f + expf(-g1))) * u1;
                *(__half2*)(g_act + abase + (size_t)row*II + col) = __floats2half2_rn(a0, a1);
            }
}

// ---------------- kernel 7: GEMM2 (a @ W2^T), scale by comb, atomicAdd into out ----------------
__global__ __launch_bounds__(128) void k_gemm2(float* __restrict__ out) {
    const int e = blockIdx.z;
    const int cnt = g_cnt[e];
    const int m0 = blockIdx.x * 64;
    if (m0 >= cnt) return;
    const int n0 = blockIdx.y * 64;   // [0, 2048)

    __shared__ __half As[64][40];
    __shared__ __half Bs[64][40];
    __shared__ int s_tok[64];

    const int tid = threadIdx.x;
    const int lane = tid & 31, warp = tid >> 5;
    const int wm = warp >> 1, wn = warp & 1;

    if (tid < 64) {
        int r = m0 + tid;
        s_tok[tid] = (r < cnt) ? g_tok[e*TT + r] : -1;
    }

    float acc[2][4][4];
    #pragma unroll
    for (int a = 0; a < 2; a++)
        #pragma unroll
        for (int b = 0; b < 4; b++)
            #pragma unroll
            for (int c = 0; c < 4; c++) acc[a][b][c] = 0.f;

    const __half* arow = g_act + ((size_t)e*TT + m0) * II;
    const __half* w2b  = g_w2h + (size_t)e*DD*II + (size_t)n0*II;

    __syncthreads();

    for (int kb = 0; kb < II/32; ++kb) {
        const int k0 = kb * 32;
        #pragma unroll
        for (int l = 0; l < 2; ++l) {
            int idx = tid + l*128;
            int row = idx >> 2, seg = idx & 3;
            *(uint4*)(&As[row][seg*8]) = *(const uint4*)(arow + (size_t)row*II + k0 + seg*8);
            *(uint4*)(&Bs[row][seg*8]) = *(const uint4*)(w2b  + (size_t)row*II + k0 + seg*8);
        }
        __syncthreads();

        #pragma unroll
        for (int kk = 0; kk < 32; kk += 16) {
            uint32_t a[2][4];
            #pragma unroll
            for (int mt = 0; mt < 2; ++mt)
                ldm_x4(a[mt], &As[wm*32 + mt*16 + (lane & 15)][kk + ((lane >> 4) << 3)]);
            uint32_t bb[4][2];
            #pragma unroll
            for (int nh = 0; nh < 2; ++nh) {
                uint32_t t4[4];
                ldm_x4(t4, &Bs[wn*32 + nh*16 + (lane & 15)][kk + ((lane >> 4) << 3)]);
                bb[nh*2+0][0] = t4[0]; bb[nh*2+1][0] = t4[1];
                bb[nh*2+0][1] = t4[2]; bb[nh*2+1][1] = t4[3];
            }
            #pragma unroll
            for (int mt = 0; mt < 2; ++mt)
                #pragma unroll
                for (int nc = 0; nc < 4; ++nc)
                    mma_f16(acc[mt][nc], a[mt], bb[nc][0], bb[nc][1]);
        }
        __syncthreads();
    }

    #pragma unroll
    for (int mt = 0; mt < 2; ++mt)
        #pragma unroll
        for (int nc = 0; nc < 4; ++nc)
            #pragma unroll
            for (int rp = 0; rp < 2; ++rp) {
                int row = wm*32 + mt*16 + (lane >> 2) + rp*8;
                if (m0 + row < cnt) {
                    int t = s_tok[row];
                    float cv = g_comb[t*EE + e];
                    int col = n0 + wn*32 + nc*8 + ((lane & 3) << 1);
                    atomicAdd(&out[(size_t)t*DD + col + 0], cv * acc[mt][nc][rp*2+0]);
                    atomicAdd(&out[(size_t)t*DD + col + 1], cv * acc[mt][nc][rp*2+1]);
                }
            }
}

// ---------------- launcher ----------------
extern "C" void kernel_launch(void* const* d_in, const int* in_sizes, int n_in,
                              void* d_out, int out_size) {
    const float* hs   = (const float*)d_in[0];
    const float* tw   = (const float*)d_in[1];
    const int*   tids = (const int*)d_in[2];
    const int*   w13  = (const int*)d_in[3];
    const int*   w13s = (const int*)d_in[4];
    const int*   w2   = (const int*)d_in[5];
    const int*   w2s  = (const int*)d_in[6];
    float* out = (float*)d_out;

    k_zero<<<(TT*DD + 255)/256, 256>>>(out);
    k_quant<<<(TT*DD + 255)/256, 256>>>(hs);
    {
        long total = (long)NW13_INT + NW2_INT;
        k_dequant<<<(unsigned)((total + 255)/256), 256>>>(w13, w13s, w2, w2s);
    }
    k_route1<<<2, 256>>>(tw, tids);
    k_route2<<<(TT*EE + 255)/256, 256>>>();
    {
        dim3 g1(TT/64, II/64, EE);      // (8, 12, 16)
        k_gemm1<<<g1, 128>>>();
        dim3 g2(TT/64, DD/64, EE);      // (8, 32, 16)
        k_gemm2<<<g2, 128>>>(out);
    }
    (void)in_sizes; (void)n_in; (void)out_size;
}

// round 5
// speedup vs baseline: 1.1468x; 1.1468x over previous
#include <cuda_runtime.h>
#include <cuda_bf16.h>
#include <cuda_fp16.h>
#include <cuda_fp8.h>
#include <cstdint>

// Problem constants
#define TT 512
#define DD 2048
#define II 768
#define EE 16
#define KTOP 8

// ---------------- device scratch (no allocations allowed) ----------------
__device__ __nv_bfloat16 g_xq[TT*DD];                    // quant-dequant x (exact bf16)
__device__ __half        g_act[(size_t)EE*TT*II];        // silu(g)*u  (fp16)
__device__ float g_comb[TT*EE];
__device__ int   g_cnt[EE];
__device__ int   g_tok[EE*TT];

// ---------------- mma / ldmatrix helpers ----------------
__device__ __forceinline__ void ldm_x4(uint32_t r[4], const void* p) {
    uint32_t addr = (uint32_t)__cvta_generic_to_shared(p);
    asm volatile("ldmatrix.sync.aligned.m8n8.x4.shared.b16 {%0,%1,%2,%3}, [%4];"
                 : "=r"(r[0]), "=r"(r[1]), "=r"(r[2]), "=r"(r[3]) : "r"(addr));
}
__device__ __forceinline__ void mma_bf16(float c[4], const uint32_t a[4], uint32_t b0, uint32_t b1) {
    asm volatile("mma.sync.aligned.m16n8k16.row.col.f32.bf16.bf16.f32 "
                 "{%0,%1,%2,%3},{%4,%5,%6,%7},{%8,%9},{%0,%1,%2,%3};"
                 : "+f"(c[0]), "+f"(c[1]), "+f"(c[2]), "+f"(c[3])
                 : "r"(a[0]), "r"(a[1]), "r"(a[2]), "r"(a[3]), "r"(b0), "r"(b1));
}
__device__ __forceinline__ void mma_f16(float c[4], const uint32_t a[4], uint32_t b0, uint32_t b1) {
    asm volatile("mma.sync.aligned.m16n8k16.row.col.f32.f16.f16.f32 "
                 "{%0,%1,%2,%3},{%4,%5,%6,%7},{%8,%9},{%0,%1,%2,%3};"
                 : "+f"(c[0]), "+f"(c[1]), "+f"(c[2]), "+f"(c[3])
                 : "r"(a[0]), "r"(a[1]), "r"(a[2]), "r"(a[3]), "r"(b0), "r"(b1));
}
__device__ __forceinline__ uint32_t bmul2(uint32_t a, uint32_t s) {
    uint32_t d; asm("mul.rn.bf16x2 %0,%1,%2;" : "=r"(d) : "r"(a), "r"(s)); return d;
}
__device__ __forceinline__ uint32_t hmul2u(uint32_t a, uint32_t s) {
    uint32_t d; asm("mul.rn.f16x2 %0,%1,%2;" : "=r"(d) : "r"(a), "r"(s)); return d;
}

// Compress 3-bit magnitudes at bits[0:3) of each byte of x into a 16-bit
// PRMT selector (4 bits per digit): m0 | m1<<4 | m2<<8 | m3<<12.
__device__ __forceinline__ uint32_t nib_sel(uint32_t x) {
    uint32_t y = x | (x >> 4);
    return __byte_perm(y, y, 0x0020);
}

// ---------------- fused fp4 dequant (PRMT LUT, exact) ----------------
// v = 4 int32s, each holding one byte = 2 fp4 nibbles (8 values total).
// Returns 4 words of bf16x2 = values [e0..e7] scaled by s2 (bf16x2 power-of-2 scale).
__device__ __forceinline__ uint4 dq8_bf16(uint4 v, uint32_t s2) {
    uint32_t t0 = __byte_perm(v.x, v.y, 0x0040);
    uint32_t t1 = __byte_perm(v.z, v.w, 0x0040);
    uint32_t p  = __byte_perm(t0, t1, 0x5410);           // [b0(x),b0(y),b0(z),b0(w)]
    uint32_t sl = nib_sel(p & 0x07070707u);              // even-elem magnitudes as selector
    uint32_t sh = nib_sel((p >> 4) & 0x07070707u);       // odd-elem magnitudes as selector
    const uint32_t LA = 0xC0800000u, LB = 0xC0804000u;   // bf16 lo bytes, mags 0-7
    const uint32_t HA = 0x3F3F3F00u, HB = 0x40404040u;   // bf16 hi bytes, mags 0-7
    uint32_t LOl = __byte_perm(LA, LB, sl);
    uint32_t HIl = __byte_perm(HA, HB, sl);
    uint32_t LOh = __byte_perm(LA, LB, sh);
    uint32_t HIh = __byte_perm(HA, HB, sh);
    HIl |= (p << 4) & 0x80808080u;                       // sign of even elems (bit3 -> bit7)
    HIh |=  p       & 0x80808080u;                       // sign of odd elems
    uint32_t Pl0 = __byte_perm(LOl, HIl, 0x5140);        // (e0,e2)
    uint32_t Pl1 = __byte_perm(LOl, HIl, 0x7362);        // (e4,e6)
    uint32_t Ph0 = __byte_perm(LOh, HIh, 0x5140);        // (e1,e3)
    uint32_t Ph1 = __byte_perm(LOh, HIh, 0x7362);        // (e5,e7)
    uint4 r;
    r.x = bmul2(__byte_perm(Pl0, Ph0, 0x5410), s2);      // (e0,e1)
    r.y = bmul2(__byte_perm(Pl0, Ph0, 0x7632), s2);      // (e2,e3)
    r.z = bmul2(__byte_perm(Pl1, Ph1, 0x5410), s2);      // (e4,e5)
    r.w = bmul2(__byte_perm(Pl1, Ph1, 0x7632), s2);      // (e6,e7)
    return r;
}
// fp16 variant (lo bytes of fp4 values in fp16 are all zero)
__device__ __forceinline__ uint4 dq8_fp16(uint4 v, uint32_t s2) {
    uint32_t t0 = __byte_perm(v.x, v.y, 0x0040);
    uint32_t t1 = __byte_perm(v.z, v.w, 0x0040);
    uint32_t p  = __byte_perm(t0, t1, 0x5410);
    uint32_t sl = nib_sel(p & 0x07070707u);
    uint32_t sh = nib_sel((p >> 4) & 0x07070707u);
    const uint32_t HA = 0x3E3C3800u, HB = 0x46444240u;   // fp16 hi bytes, mags 0-7
    uint32_t Hl = __byte_perm(HA, HB, sl);
    uint32_t Hh = __byte_perm(HA, HB, sh);
    Hl |= (p << 4) & 0x80808080u;
    Hh |=  p       & 0x80808080u;
    uint32_t A0 = __byte_perm(Hl, Hh, 0x5140);           // hi bytes of e0,e1,e2,e3
    uint32_t A1 = __byte_perm(Hl, Hh, 0x7362);           // hi bytes of e4..e7
    uint4 r;
    r.x = hmul2u(__byte_perm(A0, 0, 0x1404), s2);        // (e0,e1)
    r.y = hmul2u(__byte_perm(A0, 0, 0x3424), s2);        // (e2,e3)
    r.z = hmul2u(__byte_perm(A1, 0, 0x1404), s2);        // (e4,e5)
    r.w = hmul2u(__byte_perm(A1, 0, 0x3424), s2);        // (e6,e7)
    return r;
}

// ---------------- kernel 1: zero out + counters ----------------
__global__ void k_zero(float* __restrict__ out) {
    int i = blockIdx.x * blockDim.x + threadIdx.x;
    if (i < TT*DD) out[i] = 0.f;
    if (i < EE) g_cnt[i] = 0;
}

// ---------------- kernel 2: fp8 quant-dequant of x (warp per group of 32) ----------------
__global__ void k_quant(const float* __restrict__ x) {
    int gid = blockIdx.x * blockDim.x + threadIdx.x;
    float v = x[gid];
    float a = fabsf(v);
    #pragma unroll
    for (int off = 16; off; off >>= 1) a = fmaxf(a, __shfl_xor_sync(0xFFFFFFFFu, a, off));
    a = fmaxf(a, 0.0001f);
    float scale = a * (1.0f / 448.0f);
    unsigned bits = __float_as_uint(scale);
    unsigned exp = ((bits >> 23) & 255u) + ((bits & 0x7FFFFFu) != 0u);
    exp = min(max(exp, 1u), 254u);
    float rscale = __uint_as_float(exp << 23);
    float inv = 1.0f / rscale;
    __nv_fp8_storage_t q = __nv_cvt_float_to_fp8(v * inv, __NV_SATFINITE, __NV_E4M3);
    float dq = __half2float(__half(__nv_cvt_fp8_to_halfraw(q, __NV_E4M3))) * rscale;
    g_xq[gid] = __float2bfloat16(dq);
}

// ---------------- kernel 3: routing (combine weights + per-expert token lists) ----------------
__global__ void k_route(const float* __restrict__ tw, const int* __restrict__ tids) {
    int t = threadIdx.x;   // blockDim = 512
    float c[EE];
    #pragma unroll
    for (int e = 0; e < EE; e++) c[e] = 0.f;
    #pragma unroll
    for (int k = 0; k < KTOP; k++) c[tids[t*KTOP + k]] += tw[t*KTOP + k];
    #pragma unroll
    for (int e = 0; e < EE; e++) {
        g_comb[t*EE + e] = c[e];
        if (c[e] > 0.f) {
            int s = atomicAdd(&g_cnt[e], 1);
            g_tok[e*TT + s] = t;
        }
    }
}

// ---------------- kernel 4: GEMM1 (x @ W13^T) fused dequant + silu*up -> g_act ----------------
__global__ __launch_bounds__(128) void k_gemm1(const int* __restrict__ w13,
                                               const int* __restrict__ w13s) {
    const int e = blockIdx.z;
    const int cnt = g_cnt[e];
    const int m0 = blockIdx.x * 64;
    if (m0 >= cnt) return;
    const int n0 = blockIdx.y * 64;   // [0, 768)

    __shared__ __nv_bfloat16 As[2][64][40];
    __shared__ __nv_bfloat16 Bsm[2][2][64][40];   // [mat][buf]
    __shared__ int s_tok[64];

    const int tid = threadIdx.x;
    const int lane = tid & 31, warp = tid >> 5;
    const int wm = warp >> 1, wn = warp & 1;

    if (tid < 64) {
        int r = m0 + tid;
        s_tok[tid] = (r < cnt) ? g_tok[e*TT + r] : -1;
    }
    __syncthreads();

    // B mapping: thread handles one row-kblock of one matrix (gate/up)
    const int mat = tid >> 6, brow = tid & 63;
    const int rowg = e*(2*II) + mat*II + n0 + brow;
    const uint4* bsrc = (const uint4*)(w13 + (size_t)rowg * (DD/2));
    const int* bscale = w13s + (size_t)rowg * (DD/32);
    // A mapping: 2 uint4 per thread
    const int ar0 = tid >> 2, aseg = tid & 3;
    const int tok0 = s_tok[ar0], tok1 = s_tok[ar0 + 32];
    const uint4 z4 = make_uint4(0,0,0,0);

    float accg[2][4][4], accu[2][4][4];
    #pragma unroll
    for (int a = 0; a < 2; a++)
        #pragma unroll
        for (int b = 0; b < 4; b++)
            #pragma unroll
            for (int c = 0; c < 4; c++) { accg[a][b][c] = 0.f; accu[a][b][c] = 0.f; }

    // prologue: load kb=0
    uint4 bp[4]; int sf;
    uint4 ap0, ap1;
    #pragma unroll
    for (int j = 0; j < 4; ++j) bp[j] = bsrc[j];
    sf = bscale[0];
    ap0 = (tok0 >= 0) ? *(const uint4*)(g_xq + (size_t)tok0*DD + aseg*8) : z4;
    ap1 = (tok1 >= 0) ? *(const uint4*)(g_xq + (size_t)tok1*DD + aseg*8) : z4;

    for (int kb = 0; kb < DD/32; ++kb) {
        const int buf = kb & 1;
        // dequant + store B
        {
            uint32_t s2 = (uint32_t)(sf << 7) * 0x10001u;   // bf16 bits of 2^(sf-127)
            __nv_bfloat16* bd = &Bsm[mat][buf][brow][0];
            #pragma unroll
            for (int j = 0; j < 4; ++j)
                *(uint4*)(bd + j*8) = dq8_bf16(bp[j], s2);
        }
        // store A
        *(uint4*)(&As[buf][ar0][aseg*8])      = ap0;
        *(uint4*)(&As[buf][ar0+32][aseg*8])   = ap1;
        __syncthreads();

        // prefetch kb+1
        if (kb + 1 < DD/32) {
            const int k1 = (kb + 1) * 32;
            #pragma unroll
            for (int j = 0; j < 4; ++j) bp[j] = bsrc[(kb+1)*4 + j];
            sf = bscale[kb+1];
            ap0 = (tok0 >= 0) ? *(const uint4*)(g_xq + (size_t)tok0*DD + k1 + aseg*8) : z4;
            ap1 = (tok1 >= 0) ? *(const uint4*)(g_xq + (size_t)tok1*DD + k1 + aseg*8) : z4;
        }

        // mma on buf
        #pragma unroll
        for (int kk = 0; kk < 32; kk += 16) {
            uint32_t a[2][4];
            #pragma unroll
            for (int mt = 0; mt < 2; ++mt)
                ldm_x4(a[mt], &As[buf][wm*32 + mt*16 + (lane & 15)][kk + ((lane >> 4) << 3)]);
            uint32_t bg[4][2], bu[4][2];
            #pragma unroll
            for (int nh = 0; nh < 2; ++nh) {
                uint32_t t4[4];
                ldm_x4(t4, &Bsm[0][buf][wn*32 + nh*16 + (lane & 15)][kk + ((lane >> 4) << 3)]);
                bg[nh*2+0][0] = t4[0]; bg[nh*2+1][0] = t4[1];
                bg[nh*2+0][1] = t4[2]; bg[nh*2+1][1] = t4[3];
                ldm_x4(t4, &Bsm[1][buf][wn*32 + nh*16 + (lane & 15)][kk + ((lane >> 4) << 3)]);
                bu[nh*2+0][0] = t4[0]; bu[nh*2+1][0] = t4[1];
                bu[nh*2+0][1] = t4[2]; bu[nh*2+1][1] = t4[3];
            }
            #pragma unroll
            for (int mt = 0; mt < 2; ++mt)
                #pragma unroll
                for (int nc = 0; nc < 4; ++nc) {
                    mma_bf16(accg[mt][nc], a[mt], bg[nc][0], bg[nc][1]);
                    mma_bf16(accu[mt][nc], a[mt], bu[nc][0], bu[nc][1]);
                }
        }
    }

    // epilogue: a = silu(gate) * up -> fp16 g_act
    const size_t abase = ((size_t)e*TT + m0) * II + n0;
    #pragma unroll
    for (int mt = 0; mt < 2; ++mt)
        #pragma unroll
        for (int nc = 0; nc < 4; ++nc)
            #pragma unroll
            for (int rp = 0; rp < 2; ++rp) {
                int row = wm*32 + mt*16 + (lane >> 2) + rp*8;
                int col = wn*32 + nc*8 + ((lane & 3) << 1);
                float g0 = accg[mt][nc][rp*2+0], g1 = accg[mt][nc][rp*2+1];
                float u0 = accu[mt][nc][rp*2+0], u1 = accu[mt][nc][rp*2+1];
                float a0 = (g0 / (1.f + __expf(-g0))) * u0;
                float a1 = (g1 / (1.f + __expf(-g1))) * u1;
                *(__half2*)(g_act + abase + (size_t)row*II + col) = __floats2half2_rn(a0, a1);
            }
}

// ---------------- kernel 5: GEMM2 (a @ W2^T) fused dequant, scale by comb, atomicAdd ----------------
__global__ __launch_bounds__(128) void k_gemm2(const int* __restrict__ w2,
                                               const int* __restrict__ w2s,
                                               float* __restrict__ out) {
    const int e = blockIdx.z;
    const int cnt = g_cnt[e];
    const int m0 = blockIdx.x * 64;
    if (m0 >= cnt) return;
    const int n0 = blockIdx.y * 64;   // [0, 2048)

    __shared__ __half As[2][64][40];
    __shared__ __half Bs[2][64][40];
    __shared__ int s_tok[64];

    const int tid = threadIdx.x;
    const int lane = tid & 31, warp = tid >> 5;
    const int wm = warp >> 1, wn = warp & 1;

    if (tid < 64) {
        int r = m0 + tid;
        s_tok[tid] = (r < cnt) ? g_tok[e*TT + r] : -1;
    }
    __syncthreads();

    // B mapping: thread t covers half a row-kblock (8 ints = 16 values)
    const int brow = tid >> 1, bhalf = tid & 1;
    const int rowg = e*DD + n0 + brow;
    const int* bints = w2 + (size_t)rowg * (II/2);
    const int* bscale = w2s + (size_t)rowg * (II/32);
    // A mapping
    const int ar0 = tid >> 2, aseg = tid & 3;
    const __half* arow = g_act + ((size_t)e*TT + m0) * II;

    float acc[2][4][4];
    #pragma unroll
    for (int a = 0; a < 2; a++)
        #pragma unroll
        for (int b = 0; b < 4; b++)
            #pragma unroll
            for (int c = 0; c < 4; c++) acc[a][b][c] = 0.f;

    // prologue loads (kb=0)
    uint4 bp[2]; int sf;
    uint4 ap0, ap1;
    bp[0] = *(const uint4*)(bints + bhalf*8 + 0);
    bp[1] = *(const uint4*)(bints + bhalf*8 + 4);
    sf = bscale[0];
    ap0 = *(const uint4*)(arow + (size_t)ar0*II + aseg*8);
    ap1 = *(const uint4*)(arow + (size_t)(ar0+32)*II + aseg*8);

    for (int kb = 0; kb < II/32; ++kb) {
        const int buf = kb & 1;
        {
            uint32_t s2 = (uint32_t)((sf - 112) << 10) * 0x10001u;  // fp16 bits of 2^(sf-127)
            __half* bd = &Bs[buf][brow][bhalf*16];
            *(uint4*)(bd + 0) = dq8_fp16(bp[0], s2);
            *(uint4*)(bd + 8) = dq8_fp16(bp[1], s2);
        }
        *(uint4*)(&As[buf][ar0][aseg*8])    = ap0;
        *(uint4*)(&As[buf][ar0+32][aseg*8]) = ap1;
        __syncthreads();

        if (kb + 1 < II/32) {
            const int k1 = (kb + 1) * 32;
            bp[0] = *(const uint4*)(bints + (kb+1)*16 + bhalf*8 + 0);
            bp[1] = *(const uint4*)(bints + (kb+1)*16 + bhalf*8 + 4);
            sf = bscale[kb+1];
            ap0 = *(const uint4*)(arow + (size_t)ar0*II + k1 + aseg*8);
            ap1 = *(const uint4*)(arow + (size_t)(ar0+32)*II + k1 + aseg*8);
        }

        #pragma unroll
        for (int kk = 0; kk < 32; kk += 16) {
            uint32_t a[2][4];
            #pragma unroll
            for (int mt = 0; mt < 2; ++mt)
                ldm_x4(a[mt], &As[buf][wm*32 + mt*16 + (lane & 15)][kk + ((lane >> 4) << 3)]);
            uint32_t bb[4][2];
            #pragma unroll
            for (int nh = 0; nh < 2; ++nh) {
                uint32_t t4[4];
                ldm_x4(t4, &Bs[buf][wn*32 + nh*16 + (lane & 15)][kk + ((lane >> 4) << 3)]);
                bb[nh*2+0][0] = t4[0]; bb[nh*2+1][0] = t4[1];
                bb[nh*2+0][1] = t4[2]; bb[nh*2+1][1] = t4[3];
            }
            #pragma unroll
            for (int mt = 0; mt < 2; ++mt)
                #pragma unroll
                for (int nc = 0; nc < 4; ++nc)
                    mma_f16(acc[mt][nc], a[mt], bb[nc][0], bb[nc][1]);
        }
    }

    #pragma unroll
    for (int mt = 0; mt < 2; ++mt)
        #pragma unroll
        for (int nc = 0; nc < 4; ++nc)
            #pragma unroll
            for (int rp = 0; rp < 2; ++rp) {
                int row = wm*32 + mt*16 + (lane >> 2) + rp*8;
                if (m0 + row < cnt) {
                    int t = s_tok[row];
                    float cv = g_comb[t*EE + e];
                    int col = n0 + wn*32 + nc*8 + ((lane & 3) << 1);
                    atomicAdd(&out[(size_t)t*DD + col + 0], cv * acc[mt][nc][rp*2+0]);
                    atomicAdd(&out[(size_t)t*DD + col + 1], cv * acc[mt][nc][rp*2+1]);
                }
            }
}

// ---------------- launcher ----------------
extern "C" void kernel_launch(void* const* d_in, const int* in_sizes, int n_in,
                              void* d_out, int out_size) {
    const float* hs   = (const float*)d_in[0];
    const float* tw   = (const float*)d_in[1];
    const int*   tids = (const int*)d_in[2];
    const int*   w13  = (const int*)d_in[3];
    const int*   w13s = (const int*)d_in[4];
    const int*   w2   = (const int*)d_in[5];
    const int*   w2s  = (const int*)d_in[6];
    float* out = (float*)d_out;

    k_zero<<<(TT*DD + 255)/256, 256>>>(out);
    k_quant<<<(TT*DD + 255)/256, 256>>>(hs);
    k_route<<<1, TT>>>(tw, tids);
    {
        dim3 g1(TT/64, II/64, EE);      // (8, 12, 16)
        k_gemm1<<<g1, 128>>>(w13, w13s);
        dim3 g2(TT/64, DD/64, EE);      // (8, 32, 16)
        k_gemm2<<<g2, 128>>>(w2, w2s, out);
    }
    (void)in_sizes; (void)n_in; (void)out_size;
}

// round 6
// speedup vs baseline: 1.1726x; 1.0225x over previous
#include <cuda_runtime.h>
#include <cuda_bf16.h>
#include <cuda_fp16.h>
#include <cuda_fp8.h>
#include <cstdint>

// Problem constants
#define TT 512
#define DD 2048
#define II 768
#define EE 16
#define KTOP 8

// ---------------- device scratch (no allocations allowed) ----------------
__device__ __nv_bfloat16 g_xq[TT*DD];                    // quant-dequant x (exact bf16)
__device__ __half        g_act[(size_t)EE*TT*II];        // silu(g)*u  (fp16)
__device__ float g_comb[TT*EE];
__device__ int   g_cnt[EE];
__device__ int   g_tok[EE*TT];

// ---------------- mma / ldmatrix helpers ----------------
__device__ __forceinline__ void ldm_x4(uint32_t r[4], const void* p) {
    uint32_t addr = (uint32_t)__cvta_generic_to_shared(p);
    asm volatile("ldmatrix.sync.aligned.m8n8.x4.shared.b16 {%0,%1,%2,%3}, [%4];"
                 : "=r"(r[0]), "=r"(r[1]), "=r"(r[2]), "=r"(r[3]) : "r"(addr));
}
__device__ __forceinline__ void mma_bf16(float c[4], const uint32_t a[4], uint32_t b0, uint32_t b1) {
    asm volatile("mma.sync.aligned.m16n8k16.row.col.f32.bf16.bf16.f32 "
                 "{%0,%1,%2,%3},{%4,%5,%6,%7},{%8,%9},{%0,%1,%2,%3};"
                 : "+f"(c[0]), "+f"(c[1]), "+f"(c[2]), "+f"(c[3])
                 : "r"(a[0]), "r"(a[1]), "r"(a[2]), "r"(a[3]), "r"(b0), "r"(b1));
}
__device__ __forceinline__ void mma_f16(float c[4], const uint32_t a[4], uint32_t b0, uint32_t b1) {
    asm volatile("mma.sync.aligned.m16n8k16.row.col.f32.f16.f16.f32 "
                 "{%0,%1,%2,%3},{%4,%5,%6,%7},{%8,%9},{%0,%1,%2,%3};"
                 : "+f"(c[0]), "+f"(c[1]), "+f"(c[2]), "+f"(c[3])
                 : "r"(a[0]), "r"(a[1]), "r"(a[2]), "r"(a[3]), "r"(b0), "r"(b1));
}
__device__ __forceinline__ uint32_t bmul2(uint32_t a, uint32_t s) {
    uint32_t d; asm("mul.rn.bf16x2 %0,%1,%2;" : "=r"(d) : "r"(a), "r"(s)); return d;
}
__device__ __forceinline__ uint32_t hmul2u(uint32_t a, uint32_t s) {
    uint32_t d; asm("mul.rn.f16x2 %0,%1,%2;" : "=r"(d) : "r"(a), "r"(s)); return d;
}

// Compress 3-bit magnitudes at bits[0:3) of each byte of x into a 16-bit
// PRMT selector (4 bits per digit): m0 | m1<<4 | m2<<8 | m3<<12.
__device__ __forceinline__ uint32_t nib_sel(uint32_t x) {
    uint32_t y = x | (x >> 4);
    return __byte_perm(y, y, 0x0020);
}

// ---------------- fp4 dequant from packed word (PRMT LUT, exact) ----------------
// p = 4 packed bytes = 8 fp4 values e0..e7 (byte j -> e2j (lo nibble), e2j+1 (hi)).
// Returns 4 words of bf16x2: (e0,e1),(e2,e3),(e4,e5),(e6,e7), scaled by s2.
__device__ __forceinline__ uint4 dq8p_bf16(uint32_t p, uint32_t s2) {
    uint32_t sl = nib_sel(p & 0x07070707u);
    uint32_t sh = nib_sel((p >> 4) & 0x07070707u);
    const uint32_t LA = 0xC0800000u, LB = 0xC0804000u;   // bf16 lo bytes, mags 0-7
    const uint32_t HA = 0x3F3F3F00u, HB = 0x40404040u;   // bf16 hi bytes, mags 0-7
    uint32_t LOl = __byte_perm(LA, LB, sl);
    uint32_t HIl = __byte_perm(HA, HB, sl) | ((p << 4) & 0x80808080u);
    uint32_t LOh = __byte_perm(LA, LB, sh);
    uint32_t HIh = __byte_perm(HA, HB, sh) | (p & 0x80808080u);
    uint32_t Pl0 = __byte_perm(LOl, HIl, 0x5140);        // (e0,e2) bytes
    uint32_t Pl1 = __byte_perm(LOl, HIl, 0x7362);        // (e4,e6)
    uint32_t Ph0 = __byte_perm(LOh, HIh, 0x5140);        // (e1,e3)
    uint32_t Ph1 = __byte_perm(LOh, HIh, 0x7362);        // (e5,e7)
    uint4 r;
    r.x = bmul2(__byte_perm(Pl0, Ph0, 0x5410), s2);
    r.y = bmul2(__byte_perm(Pl0, Ph0, 0x7632), s2);
    r.z = bmul2(__byte_perm(Pl1, Ph1, 0x5410), s2);
    r.w = bmul2(__byte_perm(Pl1, Ph1, 0x7632), s2);
    return r;
}
// fp16 variant (lo bytes of fp4 values in fp16 are all zero)
__device__ __forceinline__ uint4 dq8p_fp16(uint32_t p, uint32_t s2) {
    uint32_t sl = nib_sel(p & 0x07070707u);
    uint32_t sh = nib_sel((p >> 4) & 0x07070707u);
    const uint32_t HA = 0x3E3C3800u, HB = 0x46444240u;   // fp16 hi bytes, mags 0-7
    uint32_t Hl = __byte_perm(HA, HB, sl) | ((p << 4) & 0x80808080u);
    uint32_t Hh = __byte_perm(HA, HB, sh) | (p & 0x80808080u);
    uint32_t A0 = __byte_perm(Hl, Hh, 0x5140);
    uint32_t A1 = __byte_perm(Hl, Hh, 0x7362);
    uint4 r;
    r.x = hmul2u(__byte_perm(A0, 0, 0x1404), s2);
    r.y = hmul2u(__byte_perm(A0, 0, 0x3424), s2);
    r.z = hmul2u(__byte_perm(A1, 0, 0x1404), s2);
    r.w = hmul2u(__byte_perm(A1, 0, 0x3424), s2);
    return r;
}

// Gather byte0 of 4 int32s into one word.
__device__ __forceinline__ uint32_t gb0(uint4 v) {
    uint32_t t0 = __byte_perm(v.x, v.y, 0x0040);
    uint32_t t1 = __byte_perm(v.z, v.w, 0x0040);
    return __byte_perm(t0, t1, 0x5410);
}
// Byte-transpose: out word q = byte q of p0..p3.
__device__ __forceinline__ uint32_t tb(uint32_t p0, uint32_t p1, uint32_t p2, uint32_t p3, int q) {
    uint32_t s = (uint32_t)(q | ((q + 4) << 4));
    return __byte_perm(__byte_perm(p0, p1, s), __byte_perm(p2, p3, s), 0x5410);
}
// 16 packed ints (as 4 uint4, byte0 of each int valid) -> transposed 16 bytes:
// out word q holds packed bytes {q, q+4, q+8, q+12} (byte index b covers k=2b,2b+1).
__device__ __forceinline__ uint4 pack16(const uint4 v[4]) {
    uint32_t p0 = gb0(v[0]), p1 = gb0(v[1]), p2 = gb0(v[2]), p3 = gb0(v[3]);
    uint4 r;
    r.x = tb(p0, p1, p2, p3, 0);
    r.y = tb(p0, p1, p2, p3, 1);
    r.z = tb(p0, p1, p2, p3, 2);
    r.w = tb(p0, p1, p2, p3, 3);
    return r;
}

// ---------------- kernel 1: zero out + counters ----------------
__global__ void k_zero(float* __restrict__ out) {
    int i = blockIdx.x * blockDim.x + threadIdx.x;
    if (i < TT*DD) out[i] = 0.f;
    if (i < EE) g_cnt[i] = 0;
}

// ---------------- kernel 2: fp8 quant-dequant of x (warp per group of 32) ----------------
__global__ void k_quant(const float* __restrict__ x) {
    int gid = blockIdx.x * blockDim.x + threadIdx.x;
    float v = x[gid];
    float a = fabsf(v);
    #pragma unroll
    for (int off = 16; off; off >>= 1) a = fmaxf(a, __shfl_xor_sync(0xFFFFFFFFu, a, off));
    a = fmaxf(a, 0.0001f);
    float scale = a * (1.0f / 448.0f);
    unsigned bits = __float_as_uint(scale);
    unsigned exp = ((bits >> 23) & 255u) + ((bits & 0x7FFFFFu) != 0u);
    exp = min(max(exp, 1u), 254u);
    float rscale = __uint_as_float(exp << 23);
    float inv = 1.0f / rscale;
    __nv_fp8_storage_t q = __nv_cvt_float_to_fp8(v * inv, __NV_SATFINITE, __NV_E4M3);
    float dq = __half2float(__half(__nv_cvt_fp8_to_halfraw(q, __NV_E4M3))) * rscale;
    g_xq[gid] = __float2bfloat16(dq);
}

// ---------------- kernel 3: routing ----------------
__global__ void k_route(const float* __restrict__ tw, const int* __restrict__ tids) {
    int t = threadIdx.x;   // blockDim = 512
    float c[EE];
    #pragma unroll
    for (int e = 0; e < EE; e++) c[e] = 0.f;
    #pragma unroll
    for (int k = 0; k < KTOP; k++) c[tids[t*KTOP + k]] += tw[t*KTOP + k];
    #pragma unroll
    for (int e = 0; e < EE; e++) {
        g_comb[t*EE + e] = c[e];
        if (c[e] > 0.f) {
            int s = atomicAdd(&g_cnt[e], 1);
            g_tok[e*TT + s] = t;
        }
    }
}

// ---------------- kernel 4: GEMM1 (x @ W13^T), packed-B smem, fused dequant-to-fragment ----------------
__global__ __launch_bounds__(128) void k_gemm1(const int* __restrict__ w13,
                                               const int* __restrict__ w13s) {
    const int e = blockIdx.z;
    const int cnt = g_cnt[e];
    const int m0 = blockIdx.x * 64;
    if (m0 >= cnt) return;
    const int n0 = blockIdx.y * 64;   // [0, 768)

    __shared__ __nv_bfloat16 As[2][64][40];
    __shared__ __align__(16) uint32_t Bp[2][2][64][12];  // [mat][buf][row][0-3 data,4 scale,pad]
    __shared__ int s_tok[64];

    const int tid = threadIdx.x;
    const int lane = tid & 31, warp = tid >> 5;
    const int wm = warp >> 1, wn = warp & 1;
    const int q = lane & 3, g4 = lane >> 2;

    if (tid < 64) {
        int r = m0 + tid;
        s_tok[tid] = (r < cnt) ? g_tok[e*TT + r] : -1;
    }
    __syncthreads();

    // B loader mapping: thread = one row of one matrix (gate/up)
    const int mat = tid >> 6, brow = tid & 63;
    const int rowg = e*(2*II) + mat*II + n0 + brow;
    const uint4* bsrc = (const uint4*)(w13 + (size_t)rowg * (DD/2));  // 256 uint4/row
    const int* bscale = w13s + (size_t)rowg * (DD/32);
    // A loader mapping: 2 uint4 per thread
    const int ar0 = tid >> 2, aseg = tid & 3;
    const int tok0 = s_tok[ar0], tok1 = s_tok[ar0 + 32];
    const uint4 z4 = make_uint4(0,0,0,0);

    float accg[2][4][4], accu[2][4][4];
    #pragma unroll
    for (int a = 0; a < 2; a++)
        #pragma unroll
        for (int b = 0; b < 4; b++)
            #pragma unroll
            for (int c = 0; c < 4; c++) { accg[a][b][c] = 0.f; accu[a][b][c] = 0.f; }

    // prologue loads (kb=0)
    uint4 bp[4]; int sf;
    uint4 ap0, ap1;
    #pragma unroll
    for (int j = 0; j < 4; ++j) bp[j] = bsrc[j];
    sf = bscale[0];
    ap0 = (tok0 >= 0) ? *(const uint4*)(g_xq + (size_t)tok0*DD + aseg*8) : z4;
    ap1 = (tok1 >= 0) ? *(const uint4*)(g_xq + (size_t)tok1*DD + aseg*8) : z4;

    for (int kb = 0; kb < DD/32; ++kb) {
        const int buf = kb & 1;
        // store packed B (byte-transposed) + scale word
        *(uint4*)&Bp[mat][buf][brow][0] = pack16(bp);
        Bp[mat][buf][brow][4] = (uint32_t)(sf << 7) * 0x10001u;   // bf16x2 of 2^(sf-127)
        // store A
        *(uint4*)(&As[buf][ar0][aseg*8])    = ap0;
        *(uint4*)(&As[buf][ar0+32][aseg*8]) = ap1;
        __syncthreads();

        // prefetch kb+1
        if (kb + 1 < DD/32) {
            const int k1 = (kb + 1) * 32;
            #pragma unroll
            for (int j = 0; j < 4; ++j) bp[j] = bsrc[(kb+1)*4 + j];
            sf = bscale[kb+1];
            ap0 = (tok0 >= 0) ? *(const uint4*)(g_xq + (size_t)tok0*DD + k1 + aseg*8) : z4;
            ap1 = (tok1 >= 0) ? *(const uint4*)(g_xq + (size_t)tok1*DD + k1 + aseg*8) : z4;
        }

        // A fragments for both k-halves
        uint32_t af[2][2][4];
        #pragma unroll
        for (int kh = 0; kh < 2; ++kh)
            #pragma unroll
            for (int mt = 0; mt < 2; ++mt)
                ldm_x4(af[kh][mt], &As[buf][wm*32 + mt*16 + (lane & 15)][kh*16 + ((lane >> 4) << 3)]);

        // per n-chunk: LDS packed word + scale, dequant to fragments, mma
        #pragma unroll
        for (int nc = 0; nc < 4; ++nc) {
            const int row = wn*32 + nc*8 + g4;
            const uint32_t* rg = &Bp[0][buf][row][0];
            const uint32_t* ru = &Bp[1][buf][row][0];
            uint4 bg = dq8p_bf16(rg[q], rg[4]);
            uint4 bu = dq8p_bf16(ru[q], ru[4]);
            #pragma unroll
            for (int mt = 0; mt < 2; ++mt) {
                mma_bf16(accg[mt][nc], af[0][mt], bg.x, bg.y);
                mma_bf16(accg[mt][nc], af[1][mt], bg.z, bg.w);
                mma_bf16(accu[mt][nc], af[0][mt], bu.x, bu.y);
                mma_bf16(accu[mt][nc], af[1][mt], bu.z, bu.w);
            }
        }
        __syncthreads();
    }

    // epilogue: a = silu(gate) * up -> fp16 g_act
    const size_t abase = ((size_t)e*TT + m0) * II + n0;
    #pragma unroll
    for (int mt = 0; mt < 2; ++mt)
        #pragma unroll
        for (int nc = 0; nc < 4; ++nc)
            #pragma unroll
            for (int rp = 0; rp < 2; ++rp) {
                int row = wm*32 + mt*16 + (lane >> 2) + rp*8;
                int col = wn*32 + nc*8 + ((lane & 3) << 1);
                float g0 = accg[mt][nc][rp*2+0], g1 = accg[mt][nc][rp*2+1];
                float u0 = accu[mt][nc][rp*2+0], u1 = accu[mt][nc][rp*2+1];
                float a0 = (g0 / (1.f + __expf(-g0))) * u0;
                float a1 = (g1 / (1.f + __expf(-g1))) * u1;
                *(__half2*)(g_act + abase + (size_t)row*II + col) = __floats2half2_rn(a0, a1);
            }
}

// ---------------- kernel 5: GEMM2 (a @ W2^T), packed-B smem, scale by comb, atomicAdd ----------------
__global__ __launch_bounds__(128) void k_gemm2(const int* __restrict__ w2,
                                               const int* __restrict__ w2s,
                                               float* __restrict__ out) {
    const int e = blockIdx.z;
    const int cnt = g_cnt[e];
    const int m0 = blockIdx.x * 64;
    if (m0 >= cnt) return;
    const int n0 = blockIdx.y * 64;   // [0, 2048)

    __shared__ __half As[2][64][40];
    __shared__ __align__(16) uint32_t Bp[2][64][12];   // [buf][row][0-3 data,4 scale,pad]
    __shared__ int s_tok[64];

    const int tid = threadIdx.x;
    const int lane = tid & 31, warp = tid >> 5;
    const int wm = warp >> 1, wn = warp & 1;
    const int q = lane & 3, g4 = lane >> 2;

    if (tid < 64) {
        int r = m0 + tid;
        s_tok[tid] = (r < cnt) ? g_tok[e*TT + r] : -1;
    }
    __syncthreads();

    // B loader: threads 0..63, one row each
    const int brow = tid & 63;
    const int rowg = e*DD + n0 + brow;
    const uint4* bsrc = (const uint4*)(w2 + (size_t)rowg * (II/2));   // 96 uint4/row
    const int* bscale = w2s + (size_t)rowg * (II/32);
    const bool bload = (tid < 64);
    // A loader mapping
    const int ar0 = tid >> 2, aseg = tid & 3;
    const __half* arow = g_act + ((size_t)e*TT + m0) * II;

    float acc[2][4][4];
    #pragma unroll
    for (int a = 0; a < 2; a++)
        #pragma unroll
        for (int b = 0; b < 4; b++)
            #pragma unroll
            for (int c = 0; c < 4; c++) acc[a][b][c] = 0.f;

    // prologue loads (kb=0)
    uint4 bp[4]; int sf = 0;
    uint4 ap0, ap1;
    if (bload) {
        #pragma unroll
        for (int j = 0; j < 4; ++j) bp[j] = bsrc[j];
        sf = bscale[0];
    }
    ap0 = *(const uint4*)(arow + (size_t)ar0*II + aseg*8);
    ap1 = *(const uint4*)(arow + (size_t)(ar0+32)*II + aseg*8);

    for (int kb = 0; kb < II/32; ++kb) {
        const int buf = kb & 1;
        if (bload) {
            *(uint4*)&Bp[buf][brow][0] = pack16(bp);
            Bp[buf][brow][4] = (uint32_t)((sf - 112) << 10) * 0x10001u;  // fp16x2 of 2^(sf-127)
        }
        *(uint4*)(&As[buf][ar0][aseg*8])    = ap0;
        *(uint4*)(&As[buf][ar0+32][aseg*8]) = ap1;
        __syncthreads();

        if (kb + 1 < II/32) {
            const int k1 = (kb + 1) * 32;
            if (bload) {
                #pragma unroll
                for (int j = 0; j < 4; ++j) bp[j] = bsrc[(kb+1)*4 + j];
                sf = bscale[kb+1];
            }
            ap0 = *(const uint4*)(arow + (size_t)ar0*II + k1 + aseg*8);
            ap1 = *(const uint4*)(arow + (size_t)(ar0+32)*II + k1 + aseg*8);
        }

        uint32_t af[2][2][4];
        #pragma unroll
        for (int kh = 0; kh < 2; ++kh)
            #pragma unroll
            for (int mt = 0; mt < 2; ++mt)
                ldm_x4(af[kh][mt], &As[buf][wm*32 + mt*16 + (lane & 15)][kh*16 + ((lane >> 4) << 3)]);

        #pragma unroll
        for (int nc = 0; nc < 4; ++nc) {
            const int row = wn*32 + nc*8 + g4;
            const uint32_t* rr = &Bp[buf][row][0];
            uint4 bb = dq8p_fp16(rr[q], rr[4]);
            #pragma unroll
            for (int mt = 0; mt < 2; ++mt) {
                mma_f16(acc[mt][nc], af[0][mt], bb.x, bb.y);
                mma_f16(acc[mt][nc], af[1][mt], bb.z, bb.w);
            }
        }
        __syncthreads();
    }

    #pragma unroll
    for (int mt = 0; mt < 2; ++mt)
        #pragma unroll
        for (int nc = 0; nc < 4; ++nc)
            #pragma unroll
            for (int rp = 0; rp < 2; ++rp) {
                int row = wm*32 + mt*16 + (lane >> 2) + rp*8;
                if (m0 + row < cnt) {
                    int t = s_tok[row];
                    float cv = g_comb[t*EE + e];
                    int col = n0 + wn*32 + nc*8 + ((lane & 3) << 1);
                    atomicAdd(&out[(size_t)t*DD + col + 0], cv * acc[mt][nc][rp*2+0]);
                    atomicAdd(&out[(size_t)t*DD + col + 1], cv * acc[mt][nc][rp*2+1]);
                }
            }
}

// ---------------- launcher ----------------
extern "C" void kernel_launch(void* const* d_in, const int* in_sizes, int n_in,
                              void* d_out, int out_size) {
    const float* hs   = (const float*)d_in[0];
    const float* tw   = (const float*)d_in[1];
    const int*   tids = (const int*)d_in[2];
    const int*   w13  = (const int*)d_in[3];
    const int*   w13s = (const int*)d_in[4];
    const int*   w2   = (const int*)d_in[5];
    const int*   w2s  = (const int*)d_in[6];
    float* out = (float*)d_out;

    k_zero<<<(TT*DD + 255)/256, 256>>>(out);
    k_quant<<<(TT*DD + 255)/256, 256>>>(hs);
    k_route<<<1, TT>>>(tw, tids);
    {
        dim3 g1(TT/64, II/64, EE);      // (8, 12, 16)
        k_gemm1<<<g1, 128>>>(w13, w13s);
        dim3 g2(TT/64, DD/64, EE);      // (8, 32, 16)
        k_gemm2<<<g2, 128>>>(w2, w2s, out);
    }
    (void)in_sizes; (void)n_in; (void)out_size;
}

// round 7
// speedup vs baseline: 1.3851x; 1.1812x over previous
#include <cuda_runtime.h>
#include <cuda_bf16.h>
#include <cuda_fp16.h>
#include <cuda_fp8.h>
#include <cstdint>

// Problem constants
#define TT 512
#define DD 2048
#define II 768
#define EE 16
#define KTOP 8

// ---------------- device scratch (no allocations allowed) ----------------
__device__ __nv_bfloat16 g_xq[TT*DD];                    // quant-dequant x (exact bf16)
__device__ __half        g_act[(size_t)EE*TT*II];        // silu(g)*u  (fp16)
__device__ float g_comb[TT*EE];
__device__ int   g_cnt[EE];
__device__ int   g_tok[EE*TT];

// ---------------- mma / ldmatrix helpers ----------------
__device__ __forceinline__ void ldm_x4(uint32_t r[4], const void* p) {
    uint32_t addr = (uint32_t)__cvta_generic_to_shared(p);
    asm volatile("ldmatrix.sync.aligned.m8n8.x4.shared.b16 {%0,%1,%2,%3}, [%4];"
                 : "=r"(r[0]), "=r"(r[1]), "=r"(r[2]), "=r"(r[3]) : "r"(addr));
}
__device__ __forceinline__ void mma_bf16(float c[4], const uint32_t a[4], uint32_t b0, uint32_t b1) {
    asm volatile("mma.sync.aligned.m16n8k16.row.col.f32.bf16.bf16.f32 "
                 "{%0,%1,%2,%3},{%4,%5,%6,%7},{%8,%9},{%0,%1,%2,%3};"
                 : "+f"(c[0]), "+f"(c[1]), "+f"(c[2]), "+f"(c[3])
                 : "r"(a[0]), "r"(a[1]), "r"(a[2]), "r"(a[3]), "r"(b0), "r"(b1));
}
__device__ __forceinline__ void mma_f16(float c[4], const uint32_t a[4], uint32_t b0, uint32_t b1) {
    asm volatile("mma.sync.aligned.m16n8k16.row.col.f32.f16.f16.f32 "
                 "{%0,%1,%2,%3},{%4,%5,%6,%7},{%8,%9},{%0,%1,%2,%3};"
                 : "+f"(c[0]), "+f"(c[1]), "+f"(c[2]), "+f"(c[3])
                 : "r"(a[0]), "r"(a[1]), "r"(a[2]), "r"(a[3]), "r"(b0), "r"(b1));
}
__device__ __forceinline__ uint32_t bmul2(uint32_t a, uint32_t s) {
    uint32_t d; asm("mul.rn.bf16x2 %0,%1,%2;" : "=r"(d) : "r"(a), "r"(s)); return d;
}
__device__ __forceinline__ uint32_t hmul2u(uint32_t a, uint32_t s) {
    uint32_t d; asm("mul.rn.f16x2 %0,%1,%2;" : "=r"(d) : "r"(a), "r"(s)); return d;
}

// Compress 3-bit magnitudes at bits[0:3) of each byte of x into a 16-bit
// PRMT selector (4 bits per digit): m0 | m1<<4 | m2<<8 | m3<<12.
__device__ __forceinline__ uint32_t nib_sel(uint32_t x) {
    uint32_t y = x | (x >> 4);
    return __byte_perm(y, y, 0x0020);
}

// ---------------- fp4 dequant from packed word (PRMT LUT, exact) ----------------
// p = 4 packed bytes = 8 fp4 values e0..e7. Returns (e0,e1),(e2,e3),(e4,e5),(e6,e7) * s2.
__device__ __forceinline__ uint4 dq8p_bf16(uint32_t p, uint32_t s2) {
    uint32_t sl = nib_sel(p & 0x07070707u);
    uint32_t sh = nib_sel((p >> 4) & 0x07070707u);
    const uint32_t LA = 0xC0800000u, LB = 0xC0804000u;   // bf16 lo bytes, mags 0-7
    const uint32_t HA = 0x3F3F3F00u, HB = 0x40404040u;   // bf16 hi bytes, mags 0-7
    uint32_t LOl = __byte_perm(LA, LB, sl);
    uint32_t HIl = __byte_perm(HA, HB, sl) | ((p << 4) & 0x80808080u);
    uint32_t LOh = __byte_perm(LA, LB, sh);
    uint32_t HIh = __byte_perm(HA, HB, sh) | (p & 0x80808080u);
    uint32_t Pl0 = __byte_perm(LOl, HIl, 0x5140);        // (e0,e2) bytes
    uint32_t Pl1 = __byte_perm(LOl, HIl, 0x7362);        // (e4,e6)
    uint32_t Ph0 = __byte_perm(LOh, HIh, 0x5140);        // (e1,e3)
    uint32_t Ph1 = __byte_perm(LOh, HIh, 0x7362);        // (e5,e7)
    uint4 r;
    r.x = bmul2(__byte_perm(Pl0, Ph0, 0x5410), s2);
    r.y = bmul2(__byte_perm(Pl0, Ph0, 0x7632), s2);
    r.z = bmul2(__byte_perm(Pl1, Ph1, 0x5410), s2);
    r.w = bmul2(__byte_perm(Pl1, Ph1, 0x7632), s2);
    return r;
}
// fp16 variant (lo bytes of fp4 values in fp16 are all zero)
__device__ __forceinline__ uint4 dq8p_fp16(uint32_t p, uint32_t s2) {
    uint32_t sl = nib_sel(p & 0x07070707u);
    uint32_t sh = nib_sel((p >> 4) & 0x07070707u);
    const uint32_t HA = 0x3E3C3800u, HB = 0x46444240u;   // fp16 hi bytes, mags 0-7
    uint32_t Hl = __byte_perm(HA, HB, sl) | ((p << 4) & 0x80808080u);
    uint32_t Hh = __byte_perm(HA, HB, sh) | (p & 0x80808080u);
    uint32_t A0 = __byte_perm(Hl, Hh, 0x5140);
    uint32_t A1 = __byte_perm(Hl, Hh, 0x7362);
    uint4 r;
    r.x = hmul2u(__byte_perm(A0, 0, 0x1404), s2);
    r.y = hmul2u(__byte_perm(A0, 0, 0x3424), s2);
    r.z = hmul2u(__byte_perm(A1, 0, 0x1404), s2);
    r.w = hmul2u(__byte_perm(A1, 0, 0x3424), s2);
    return r;
}

// Gather byte0 of 4 int32s into one word.
__device__ __forceinline__ uint32_t gb0(uint4 v) {
    uint32_t t0 = __byte_perm(v.x, v.y, 0x0040);
    uint32_t t1 = __byte_perm(v.z, v.w, 0x0040);
    return __byte_perm(t0, t1, 0x5410);
}
// Byte-transpose: out word = byte q of each of p0..p3.
__device__ __forceinline__ uint32_t tb(uint32_t p0, uint32_t p1, uint32_t p2, uint32_t p3, int q) {
    uint32_t s = (uint32_t)(q | ((q + 4) << 4));
    return __byte_perm(__byte_perm(p0, p1, s), __byte_perm(p2, p3, s), 0x5410);
}

// ---------------- kernel 1: zero out + counters ----------------
__global__ void k_zero(float* __restrict__ out) {
    int i = blockIdx.x * blockDim.x + threadIdx.x;
    if (i < TT*DD) out[i] = 0.f;
    if (i < EE) g_cnt[i] = 0;
}

// ---------------- kernel 2: fp8 quant-dequant of x (warp per group of 32) ----------------
__global__ void k_quant(const float* __restrict__ x) {
    int gid = blockIdx.x * blockDim.x + threadIdx.x;
    float v = x[gid];
    float a = fabsf(v);
    #pragma unroll
    for (int off = 16; off; off >>= 1) a = fmaxf(a, __shfl_xor_sync(0xFFFFFFFFu, a, off));
    a = fmaxf(a, 0.0001f);
    float scale = a * (1.0f / 448.0f);
    unsigned bits = __float_as_uint(scale);
    unsigned exp = ((bits >> 23) & 255u) + ((bits & 0x7FFFFFu) != 0u);
    exp = min(max(exp, 1u), 254u);
    float rscale = __uint_as_float(exp << 23);
    float inv = 1.0f / rscale;
    __nv_fp8_storage_t q = __nv_cvt_float_to_fp8(v * inv, __NV_SATFINITE, __NV_E4M3);
    float dq = __half2float(__half(__nv_cvt_fp8_to_halfraw(q, __NV_E4M3))) * rscale;
    g_xq[gid] = __float2bfloat16(dq);
}

// ---------------- kernel 3: routing ----------------
__global__ void k_route(const float* __restrict__ tw, const int* __restrict__ tids) {
    int t = threadIdx.x;   // blockDim = 512
    float c[EE];
    #pragma unroll
    for (int e = 0; e < EE; e++) c[e] = 0.f;
    #pragma unroll
    for (int k = 0; k < KTOP; k++) c[tids[t*KTOP + k]] += tw[t*KTOP + k];
    #pragma unroll
    for (int e = 0; e < EE; e++) {
        g_comb[t*EE + e] = c[e];
        if (c[e] > 0.f) {
            int s = atomicAdd(&g_cnt[e], 1);
            g_tok[e*TT + s] = t;
        }
    }
}

// ---------------- kernel 4: GEMM1 (x @ W13^T), coalesced loads, packed-B smem ----------------
// K chunked by 64 (2 mma k-blocks per chunk, 32 chunks)
__global__ __launch_bounds__(128, 3) void k_gemm1(const int* __restrict__ w13,
                                                  const int* __restrict__ w13s) {
    const int e = blockIdx.z;
    const int cnt = g_cnt[e];
    const int m0 = blockIdx.x * 64;
    if (m0 >= cnt) return;
    const int n0 = blockIdx.y * 64;   // [0, 768)

    __shared__ __nv_bfloat16 As[2][64][72];              // 64 rows x 64 K-chunk (+pad)
    __shared__ uint32_t Bp[2][128][12];                  // [buf][matrow][seg0-7, s2kb0, s2kb1, pad]
    __shared__ int s_tok[64];

    const int tid = threadIdx.x;
    const int lane = tid & 31, warp = tid >> 5;
    const int wm = warp >> 1, wn = warp & 1;
    const int q = lane & 3, g4 = lane >> 2;
    const int rbase = tid >> 3, seg = tid & 7;           // loader mapping

    if (tid < 64) {
        int r = m0 + tid;
        s_tok[tid] = (r < cnt) ? g_tok[e*TT + r] : -1;
    }
    __syncthreads();

    // B row global index for loader row rc (0..127): mat = rc>>6
    // scale row for this thread (one matrow each)
    const int srowg = e*2*II + (tid >> 6)*II + n0 + (tid & 63);
    const int* sptr = w13s + (size_t)srowg * (DD/32);
    // A tokens for this thread's 4 rows
    int atok[4];
    #pragma unroll
    for (int i = 0; i < 4; ++i) atok[i] = s_tok[rbase + 16*i];
    const uint4 z4 = make_uint4(0,0,0,0);

    float accg[2][4][4], accu[2][4][4];
    #pragma unroll
    for (int a = 0; a < 2; a++)
        #pragma unroll
        for (int b = 0; b < 4; b++)
            #pragma unroll
            for (int c = 0; c < 4; c++) { accg[a][b][c] = 0.f; accu[a][b][c] = 0.f; }

    // ---- prefetch chunk 0 ----
    uint32_t bw[8];
    uint2 s2w;
    uint4 aw[4];
    {
        #pragma unroll
        for (int i = 0; i < 8; ++i) {
            int rc = rbase + 16*i;
            int rowg = e*2*II + (rc >> 6)*II + n0 + (rc & 63);
            bw[i] = gb0(*((const uint4*)(w13 + (size_t)rowg * (DD/2)) + seg));
        }
        int2 sf = *(const int2*)(sptr);
        s2w.x = (uint32_t)(sf.x << 7) * 0x10001u;
        s2w.y = (uint32_t)(sf.y << 7) * 0x10001u;
        #pragma unroll
        for (int i = 0; i < 4; ++i)
            aw[i] = (atok[i] >= 0) ? *(const uint4*)(g_xq + (size_t)atok[i]*DD + seg*8) : z4;
    }

    for (int c = 0; c < DD/64; ++c) {
        const int buf = c & 1;
        // store chunk c
        #pragma unroll
        for (int i = 0; i < 8; ++i) Bp[buf][rbase + 16*i][seg] = bw[i];
        Bp[buf][tid][8] = s2w.x;
        Bp[buf][tid][9] = s2w.y;
        #pragma unroll
        for (int i = 0; i < 4; ++i)
            *(uint4*)(&As[buf][rbase + 16*i][seg*8]) = aw[i];
        __syncthreads();

        // prefetch chunk c+1
        if (c + 1 < DD/64) {
            #pragma unroll
            for (int i = 0; i < 8; ++i) {
                int rc = rbase + 16*i;
                int rowg = e*2*II + (rc >> 6)*II + n0 + (rc & 63);
                bw[i] = gb0(*((const uint4*)(w13 + (size_t)rowg * (DD/2)) + (c+1)*8 + seg));
            }
            int2 sf = *(const int2*)(sptr + 2*(c+1));
            s2w.x = (uint32_t)(sf.x << 7) * 0x10001u;
            s2w.y = (uint32_t)(sf.y << 7) * 0x10001u;
            #pragma unroll
            for (int i = 0; i < 4; ++i)
                aw[i] = (atok[i] >= 0)
                      ? *(const uint4*)(g_xq + (size_t)atok[i]*DD + (c+1)*64 + seg*8) : z4;
        }

        // compute 2 k-blocks of chunk c
        #pragma unroll
        for (int kb = 0; kb < 2; ++kb) {
            uint32_t af[2][4];  // [kh][frag] for mt below
            uint32_t af1[2][4];
            #pragma unroll
            for (int kh = 0; kh < 2; ++kh) {
                ldm_x4(af[kh],  &As[buf][wm*32 + 0*16 + (lane & 15)][kb*32 + kh*16 + ((lane >> 4) << 3)]);
                ldm_x4(af1[kh], &As[buf][wm*32 + 1*16 + (lane & 15)][kb*32 + kh*16 + ((lane >> 4) << 3)]);
            }
            #pragma unroll
            for (int nc = 0; nc < 4; ++nc) {
                const int rowB = wn*32 + nc*8 + g4;
                uint4 wg = *(uint4*)&Bp[buf][rowB][4*kb];
                uint4 wu = *(uint4*)&Bp[buf][64 + rowB][4*kb];
                uint32_t sg = Bp[buf][rowB][8 + kb];
                uint32_t su = Bp[buf][64 + rowB][8 + kb];
                uint4 bg = dq8p_bf16(tb(wg.x, wg.y, wg.z, wg.w, q), sg);
                uint4 bu = dq8p_bf16(tb(wu.x, wu.y, wu.z, wu.w, q), su);
                mma_bf16(accg[0][nc], af[0],  bg.x, bg.y);
                mma_bf16(accg[0][nc], af[1],  bg.z, bg.w);
                mma_bf16(accg[1][nc], af1[0], bg.x, bg.y);
                mma_bf16(accg[1][nc], af1[1], bg.z, bg.w);
                mma_bf16(accu[0][nc], af[0],  bu.x, bu.y);
                mma_bf16(accu[0][nc], af[1],  bu.z, bu.w);
                mma_bf16(accu[1][nc], af1[0], bu.x, bu.y);
                mma_bf16(accu[1][nc], af1[1], bu.z, bu.w);
            }
        }
        __syncthreads();
    }

    // epilogue: a = silu(gate) * up -> fp16 g_act
    const size_t abase = ((size_t)e*TT + m0) * II + n0;
    #pragma unroll
    for (int mt = 0; mt < 2; ++mt)
        #pragma unroll
        for (int nc = 0; nc < 4; ++nc)
            #pragma unroll
            for (int rp = 0; rp < 2; ++rp) {
                int row = wm*32 + mt*16 + (lane >> 2) + rp*8;
                int col = wn*32 + nc*8 + ((lane & 3) << 1);
                float g0 = accg[mt][nc][rp*2+0], g1 = accg[mt][nc][rp*2+1];
                float u0 = accu[mt][nc][rp*2+0], u1 = accu[mt][nc][rp*2+1];
                float a0 = (g0 / (1.f + __expf(-g0))) * u0;
                float a1 = (g1 / (1.f + __expf(-g1))) * u1;
                *(__half2*)(g_act + abase + (size_t)row*II + col) = __floats2half2_rn(a0, a1);
            }
}

// ---------------- kernel 5: GEMM2 (a @ W2^T), coalesced, packed-B, atomicAdd ----------------
// K chunked by 64 (12 chunks)
__global__ __launch_bounds__(128, 3) void k_gemm2(const int* __restrict__ w2,
                                                  const int* __restrict__ w2s,
                                                  float* __restrict__ out) {
    const int e = blockIdx.z;
    const int cnt = g_cnt[e];
    const int m0 = blockIdx.x * 64;
    if (m0 >= cnt) return;
    const int n0 = blockIdx.y * 64;   // [0, 2048)

    __shared__ __half As[2][64][72];
    __shared__ uint32_t Bp[2][64][12];
    __shared__ int s_tok[64];

    const int tid = threadIdx.x;
    const int lane = tid & 31, warp = tid >> 5;
    const int wm = warp >> 1, wn = warp & 1;
    const int q = lane & 3, g4 = lane >> 2;
    const int rbase = tid >> 3, seg = tid & 7;

    if (tid < 64) {
        int r = m0 + tid;
        s_tok[tid] = (r < cnt) ? g_tok[e*TT + r] : -1;
    }
    __syncthreads();

    const __half* arow = g_act + ((size_t)e*TT + m0) * II;
    const int* sptr = (tid < 64) ? (w2s + (size_t)(e*DD + n0 + tid) * (II/32)) : 0;

    float acc[2][4][4];
    #pragma unroll
    for (int a = 0; a < 2; a++)
        #pragma unroll
        for (int b = 0; b < 4; b++)
            #pragma unroll
            for (int c = 0; c < 4; c++) acc[a][b][c] = 0.f;

    // ---- prefetch chunk 0 ----
    uint32_t bw[4];
    uint2 s2w = make_uint2(0,0);
    uint4 aw[4];
    {
        #pragma unroll
        for (int i = 0; i < 4; ++i) {
            int rc = rbase + 16*i;                         // 0..63
            int rowg = e*DD + n0 + rc;
            bw[i] = gb0(*((const uint4*)(w2 + (size_t)rowg * (II/2)) + seg));
        }
        if (tid < 64) {
            int2 sf = *(const int2*)(sptr);
            s2w.x = (uint32_t)((sf.x - 112) << 10) * 0x10001u;
            s2w.y = (uint32_t)((sf.y - 112) << 10) * 0x10001u;
        }
        #pragma unroll
        for (int i = 0; i < 4; ++i)
            aw[i] = *(const uint4*)(arow + (size_t)(rbase + 16*i)*II + seg*8);
    }

    for (int c = 0; c < II/64; ++c) {
        const int buf = c & 1;
        #pragma unroll
        for (int i = 0; i < 4; ++i) Bp[buf][rbase + 16*i][seg] = bw[i];
        if (tid < 64) {
            Bp[buf][tid][8] = s2w.x;
            Bp[buf][tid][9] = s2w.y;
        }
        #pragma unroll
        for (int i = 0; i < 4; ++i)
            *(uint4*)(&As[buf][rbase + 16*i][seg*8]) = aw[i];
        __syncthreads();

        if (c + 1 < II/64) {
            #pragma unroll
            for (int i = 0; i < 4; ++i) {
                int rc = rbase + 16*i;
                int rowg = e*DD + n0 + rc;
                bw[i] = gb0(*((const uint4*)(w2 + (size_t)rowg * (II/2)) + (c+1)*8 + seg));
            }
            if (tid < 64) {
                int2 sf = *(const int2*)(sptr + 2*(c+1));
                s2w.x = (uint32_t)((sf.x - 112) << 10) * 0x10001u;
                s2w.y = (uint32_t)((sf.y - 112) << 10) * 0x10001u;
            }
            #pragma unroll
            for (int i = 0; i < 4; ++i)
                aw[i] = *(const uint4*)(arow + (size_t)(rbase + 16*i)*II + (c+1)*64 + seg*8);
        }

        #pragma unroll
        for (int kb = 0; kb < 2; ++kb) {
            uint32_t af[2][4], af1[2][4];
            #pragma unroll
            for (int kh = 0; kh < 2; ++kh) {
                ldm_x4(af[kh],  &As[buf][wm*32 + 0*16 + (lane & 15)][kb*32 + kh*16 + ((lane >> 4) << 3)]);
                ldm_x4(af1[kh], &As[buf][wm*32 + 1*16 + (lane & 15)][kb*32 + kh*16 + ((lane >> 4) << 3)]);
            }
            #pragma unroll
            for (int nc = 0; nc < 4; ++nc) {
                const int rowB = wn*32 + nc*8 + g4;
                uint4 wb = *(uint4*)&Bp[buf][rowB][4*kb];
                uint32_t sb = Bp[buf][rowB][8 + kb];
                uint4 bb = dq8p_fp16(tb(wb.x, wb.y, wb.z, wb.w, q), sb);
                mma_f16(acc[0][nc], af[0],  bb.x, bb.y);
                mma_f16(acc[0][nc], af[1],  bb.z, bb.w);
                mma_f16(acc[1][nc], af1[0], bb.x, bb.y);
                mma_f16(acc[1][nc], af1[1], bb.z, bb.w);
            }
        }
        __syncthreads();
    }

    #pragma unroll
    for (int mt = 0; mt < 2; ++mt)
        #pragma unroll
        for (int nc = 0; nc < 4; ++nc)
            #pragma unroll
            for (int rp = 0; rp < 2; ++rp) {
                int row = wm*32 + mt*16 + (lane >> 2) + rp*8;
                if (m0 + row < cnt) {
                    int t = s_tok[row];
                    float cv = g_comb[t*EE + e];
                    int col = n0 + wn*32 + nc*8 + ((lane & 3) << 1);
                    atomicAdd(&out[(size_t)t*DD + col + 0], cv * acc[mt][nc][rp*2+0]);
                    atomicAdd(&out[(size_t)t*DD + col + 1], cv * acc[mt][nc][rp*2+1]);
                }
            }
}

// ---------------- launcher ----------------
extern "C" void kernel_launch(void* const* d_in, const int* in_sizes, int n_in,
                              void* d_out, int out_size) {
    const float* hs   = (const float*)d_in[0];
    const float* tw   = (const float*)d_in[1];
    const int*   tids = (const int*)d_in[2];
    const int*   w13  = (const int*)d_in[3];
    const int*   w13s = (const int*)d_in[4];
    const int*   w2   = (const int*)d_in[5];
    const int*   w2s  = (const int*)d_in[6];
    float* out = (float*)d_out;

    k_zero<<<(TT*DD + 255)/256, 256>>>(out);
    k_quant<<<(TT*DD + 255)/256, 256>>>(hs);
    k_route<<<1, TT>>>(tw, tids);
    {
        dim3 g1(TT/64, II/64, EE);      // (8, 12, 16)
        k_gemm1<<<g1, 128>>>(w13, w13s);
        dim3 g2(TT/64, DD/64, EE);      // (8, 32, 16)
        k_gemm2<<<g2, 128>>>(w2, w2s, out);
    }
    (void)in_sizes; (void)n_in; (void)out_size;
}

// round 10
// speedup vs baseline: 1.5613x; 1.1272x over previous
#include <cuda_runtime.h>
#include <cuda_bf16.h>
#include <cuda_fp16.h>
#include <cuda_fp8.h>
#include <cstdint>

// Problem constants
#define TT 512
#define DD 2048
#define II 768
#define EE 16
#define KTOP 8

// ---------------- device scratch (no allocations allowed) ----------------
__device__ __nv_bfloat16 g_xq[TT*DD];                    // quant-dequant x (exact bf16)
__device__ __half        g_act[(size_t)EE*TT*II];        // silu(g)*u  (fp16)
__device__ float g_comb[TT*EE];
__device__ int   g_cnt[EE];
__device__ int   g_tok[EE*TT];

// ---------------- mma / ldmatrix / cp.async helpers ----------------
__device__ __forceinline__ void ldm_x4(uint32_t r[4], const void* p) {
    uint32_t addr = (uint32_t)__cvta_generic_to_shared(p);
    asm volatile("ldmatrix.sync.aligned.m8n8.x4.shared.b16 {%0,%1,%2,%3}, [%4];"
                 : "=r"(r[0]), "=r"(r[1]), "=r"(r[2]), "=r"(r[3]) : "r"(addr));
}
__device__ __forceinline__ void mma_bf16(float c[4], const uint32_t a[4], uint32_t b0, uint32_t b1) {
    asm volatile("mma.sync.aligned.m16n8k16.row.col.f32.bf16.bf16.f32 "
                 "{%0,%1,%2,%3},{%4,%5,%6,%7},{%8,%9},{%0,%1,%2,%3};"
                 : "+f"(c[0]), "+f"(c[1]), "+f"(c[2]), "+f"(c[3])
                 : "r"(a[0]), "r"(a[1]), "r"(a[2]), "r"(a[3]), "r"(b0), "r"(b1));
}
__device__ __forceinline__ void mma_f16(float c[4], const uint32_t a[4], uint32_t b0, uint32_t b1) {
    asm volatile("mma.sync.aligned.m16n8k16.row.col.f32.f16.f16.f32 "
                 "{%0,%1,%2,%3},{%4,%5,%6,%7},{%8,%9},{%0,%1,%2,%3};"
                 : "+f"(c[0]), "+f"(c[1]), "+f"(c[2]), "+f"(c[3])
                 : "r"(a[0]), "r"(a[1]), "r"(a[2]), "r"(a[3]), "r"(b0), "r"(b1));
}
__device__ __forceinline__ uint32_t bmul2(uint32_t a, uint32_t s) {
    uint32_t d; asm("mul.rn.bf16x2 %0,%1,%2;" : "=r"(d) : "r"(a), "r"(s)); return d;
}
__device__ __forceinline__ uint32_t hmul2u(uint32_t a, uint32_t s) {
    uint32_t d; asm("mul.rn.f16x2 %0,%1,%2;" : "=r"(d) : "r"(a), "r"(s)); return d;
}
// cp.async 16B with zero-fill control (sz = 16 normal, 0 -> all zeros)
__device__ __forceinline__ void cpa16(void* dst, const void* src, int sz) {
    uint32_t d = (uint32_t)__cvta_generic_to_shared(dst);
    asm volatile("cp.async.cg.shared.global [%0], [%1], 16, %2;" :: "r"(d), "l"(src), "r"(sz));
}
#define CP_COMMIT() asm volatile("cp.async.commit_group;" ::: "memory")
#define CP_WAIT0()  asm volatile("cp.async.wait_group 0;" ::: "memory")

// Compress 3-bit magnitudes at bits[0:3) of each byte of x into a 16-bit
// PRMT selector (4 bits per digit): m0 | m1<<4 | m2<<8 | m3<<12.
__device__ __forceinline__ uint32_t nib_sel(uint32_t x) {
    uint32_t y = x | (x >> 4);
    return __byte_perm(y, y, 0x0020);
}

// ---------------- fp4 dequant from packed word (PRMT LUT, exact) ----------------
// p = 4 packed bytes = 8 fp4 values e0..e7. Returns (e0,e1),(e2,e3),(e4,e5),(e6,e7) * s2.
__device__ __forceinline__ uint4 dq8p_bf16(uint32_t p, uint32_t s2) {
    uint32_t sl = nib_sel(p & 0x07070707u);
    uint32_t sh = nib_sel((p >> 4) & 0x07070707u);
    const uint32_t LA = 0xC0800000u, LB = 0xC0804000u;   // bf16 lo bytes, mags 0-7
    const uint32_t HA = 0x3F3F3F00u, HB = 0x40404040u;   // bf16 hi bytes, mags 0-7
    uint32_t LOl = __byte_perm(LA, LB, sl);
    uint32_t HIl = __byte_perm(HA, HB, sl) | ((p << 4) & 0x80808080u);
    uint32_t LOh = __byte_perm(LA, LB, sh);
    uint32_t HIh = __byte_perm(HA, HB, sh) | (p & 0x80808080u);
    uint32_t Pl0 = __byte_perm(LOl, HIl, 0x5140);        // (e0,e2) bytes
    uint32_t Pl1 = __byte_perm(LOl, HIl, 0x7362);        // (e4,e6)
    uint32_t Ph0 = __byte_perm(LOh, HIh, 0x5140);        // (e1,e3)
    uint32_t Ph1 = __byte_perm(LOh, HIh, 0x7362);        // (e5,e7)
    uint4 r;
    r.x = bmul2(__byte_perm(Pl0, Ph0, 0x5410), s2);
    r.y = bmul2(__byte_perm(Pl0, Ph0, 0x7632), s2);
    r.z = bmul2(__byte_perm(Pl1, Ph1, 0x5410), s2);
    r.w = bmul2(__byte_perm(Pl1, Ph1, 0x7632), s2);
    return r;
}
// fp16 variant (lo bytes of fp4 values in fp16 are all zero)
__device__ __forceinline__ uint4 dq8p_fp16(uint32_t p, uint32_t s2) {
    uint32_t sl = nib_sel(p & 0x07070707u);
    uint32_t sh = nib_sel((p >> 4) & 0x07070707u);
    const uint32_t HA = 0x3E3C3800u, HB = 0x46444240u;   // fp16 hi bytes, mags 0-7
    uint32_t Hl = __byte_perm(HA, HB, sl) | ((p << 4) & 0x80808080u);
    uint32_t Hh = __byte_perm(HA, HB, sh) | (p & 0x80808080u);
    uint32_t A0 = __byte_perm(Hl, Hh, 0x5140);
    uint32_t A1 = __byte_perm(Hl, Hh, 0x7362);
    uint4 r;
    r.x = hmul2u(__byte_perm(A0, 0, 0x1404), s2);
    r.y = hmul2u(__byte_perm(A0, 0, 0x3424), s2);
    r.z = hmul2u(__byte_perm(A1, 0, 0x1404), s2);
    r.w = hmul2u(__byte_perm(A1, 0, 0x3424), s2);
    return r;
}

// Gather byte0 of 4 int32s into one word.
__device__ __forceinline__ uint32_t gb0(uint4 v) {
    uint32_t t0 = __byte_perm(v.x, v.y, 0x0040);
    uint32_t t1 = __byte_perm(v.z, v.w, 0x0040);
    return __byte_perm(t0, t1, 0x5410);
}
// Byte-transpose: out word = byte q of each of p0..p3.
__device__ __forceinline__ uint32_t tb(uint32_t p0, uint32_t p1, uint32_t p2, uint32_t p3, int q) {
    uint32_t s = (uint32_t)(q | ((q + 4) << 4));
    return __byte_perm(__byte_perm(p0, p1, s), __byte_perm(p2, p3, s), 0x5410);
}

// ---------------- kernel 1: zero out + counters ----------------
__global__ void k_zero(float* __restrict__ out) {
    int i = blockIdx.x * blockDim.x + threadIdx.x;
    if (i < TT*DD) out[i] = 0.f;
    if (i < EE) g_cnt[i] = 0;
}

// ---------------- kernel 2: fp8 quant-dequant of x (warp per group of 32) ----------------
__global__ void k_quant(const float* __restrict__ x) {
    int gid = blockIdx.x * blockDim.x + threadIdx.x;
    float v = x[gid];
    float a = fabsf(v);
    #pragma unroll
    for (int off = 16; off; off >>= 1) a = fmaxf(a, __shfl_xor_sync(0xFFFFFFFFu, a, off));
    a = fmaxf(a, 0.0001f);
    float scale = a * (1.0f / 448.0f);
    unsigned bits = __float_as_uint(scale);
    unsigned exp = ((bits >> 23) & 255u) + ((bits & 0x7FFFFFu) != 0u);
    exp = min(max(exp, 1u), 254u);
    float rscale = __uint_as_float(exp << 23);
    float inv = 1.0f / rscale;
    __nv_fp8_storage_t q = __nv_cvt_float_to_fp8(v * inv, __NV_SATFINITE, __NV_E4M3);
    float dq = __half2float(__half(__nv_cvt_fp8_to_halfraw(q, __NV_E4M3))) * rscale;
    g_xq[gid] = __float2bfloat16(dq);
}

// ---------------- kernel 3: routing ----------------
__global__ void k_route(const float* __restrict__ tw, const int* __restrict__ tids) {
    int t = threadIdx.x;   // blockDim = 512
    float c[EE];
    #pragma unroll
    for (int e = 0; e < EE; e++) c[e] = 0.f;
    #pragma unroll
    for (int k = 0; k < KTOP; k++) c[tids[t*KTOP + k]] += tw[t*KTOP + k];
    #pragma unroll
    for (int e = 0; e < EE; e++) {
        g_comb[t*EE + e] = c[e];
        if (c[e] > 0.f) {
            int s = atomicAdd(&g_cnt[e], 1);
            g_tok[e*TT + s] = t;
        }
    }
}

// ---------------- kernel 4: GEMM1 (x @ W13^T), warp-n-strips, cp.async A ----------------
// K chunked by 64 (2 mma k-blocks per chunk, 32 chunks)
__global__ __launch_bounds__(128, 4) void k_gemm1(const int* __restrict__ w13,
                                                  const int* __restrict__ w13s) {
    const int e = blockIdx.z;
    const int cnt = g_cnt[e];
    const int m0 = blockIdx.x * 64;
    if (m0 >= cnt) return;
    const int n0 = blockIdx.y * 64;   // [0, 768)

    __shared__ __align__(16) __nv_bfloat16 As[2][64][72];
    __shared__ uint32_t Bp[2][128][12];   // [buf][matrow][seg0-7, s2kb0, s2kb1, pad]
    __shared__ int s_tok[64];

    const int tid = threadIdx.x;
    const int lane = tid & 31, warp = tid >> 5;          // warp owns n-strip [warp*16, +16)
    const int q = lane & 3, g4 = lane >> 2;
    const int rbase = tid >> 3, seg = tid & 7;           // loader mapping

    if (tid < 64) {
        int r = m0 + tid;
        s_tok[tid] = (r < cnt) ? g_tok[e*TT + r] : -1;
    }
    __syncthreads();

    const int srowg = e*2*II + (tid >> 6)*II + n0 + (tid & 63);
    const int* sptr = w13s + (size_t)srowg * (DD/32);
    int atok[4];
    #pragma unroll
    for (int i = 0; i < 4; ++i) atok[i] = s_tok[rbase + 16*i];

    float accg[4][2][4], accu[4][2][4];
    #pragma unroll
    for (int a = 0; a < 4; a++)
        #pragma unroll
        for (int b = 0; b < 2; b++)
            #pragma unroll
            for (int c = 0; c < 4; c++) { accg[a][b][c] = 0.f; accu[a][b][c] = 0.f; }

    // ---- prefetch chunk 0 ----
    uint32_t bw[8];
    uint2 s2w;
    #pragma unroll
    for (int i = 0; i < 4; ++i) {
        const void* src = (atok[i] >= 0) ? (const void*)(g_xq + (size_t)atok[i]*DD + seg*8)
                                         : (const void*)g_xq;
        cpa16(&As[0][rbase + 16*i][seg*8], src, (atok[i] >= 0) ? 16 : 0);
    }
    CP_COMMIT();
    #pragma unroll
    for (int i = 0; i < 8; ++i) {
        int rc = rbase + 16*i;
        int rowg = e*2*II + (rc >> 6)*II + n0 + (rc & 63);
        bw[i] = gb0(*((const uint4*)(w13 + (size_t)rowg * (DD/2)) + seg));
    }
    {
        int2 sf = *(const int2*)(sptr);
        s2w.x = (uint32_t)(sf.x << 7) * 0x10001u;
        s2w.y = (uint32_t)(sf.y << 7) * 0x10001u;
    }

    for (int c = 0; c < DD/64; ++c) {
        const int buf = c & 1;
        CP_WAIT0();                                      // A(c) landed
        #pragma unroll
        for (int i = 0; i < 8; ++i) Bp[buf][rbase + 16*i][seg] = bw[i];
        Bp[buf][tid][8] = s2w.x;
        Bp[buf][tid][9] = s2w.y;
        __syncthreads();

        if (c + 1 < DD/64) {
            #pragma unroll
            for (int i = 0; i < 4; ++i) {
                const void* src = (atok[i] >= 0)
                    ? (const void*)(g_xq + (size_t)atok[i]*DD + (c+1)*64 + seg*8)
                    : (const void*)g_xq;
                cpa16(&As[buf^1][rbase + 16*i][seg*8], src, (atok[i] >= 0) ? 16 : 0);
            }
            CP_COMMIT();
            #pragma unroll
            for (int i = 0; i < 8; ++i) {
                int rc = rbase + 16*i;
                int rowg = e*2*II + (rc >> 6)*II + n0 + (rc & 63);
                bw[i] = gb0(*((const uint4*)(w13 + (size_t)rowg * (DD/2)) + (c+1)*8 + seg));
            }
            int2 sf = *(const int2*)(sptr + 2*(c+1));
            s2w.x = (uint32_t)(sf.x << 7) * 0x10001u;
            s2w.y = (uint32_t)(sf.y << 7) * 0x10001u;
        }

        // compute chunk c: 2 k-blocks of 32
        #pragma unroll
        for (int kb = 0; kb < 2; ++kb) {
            uint4 bg[2], bu[2];
            #pragma unroll
            for (int nc = 0; nc < 2; ++nc) {
                const int rowB = warp*16 + nc*8 + g4;
                uint4 wg = *(uint4*)&Bp[buf][rowB][4*kb];
                uint4 wu = *(uint4*)&Bp[buf][64 + rowB][4*kb];
                uint32_t sg = Bp[buf][rowB][8 + kb];
                uint32_t su = Bp[buf][64 + rowB][8 + kb];
                bg[nc] = dq8p_bf16(tb(wg.x, wg.y, wg.z, wg.w, q), sg);
                bu[nc] = dq8p_bf16(tb(wu.x, wu.y, wu.z, wu.w, q), su);
            }
            #pragma unroll
            for (int kh = 0; kh < 2; ++kh) {
                #pragma unroll
                for (int mt = 0; mt < 4; ++mt) {
                    uint32_t af[4];
                    ldm_x4(af, &As[buf][mt*16 + (lane & 15)][kb*32 + kh*16 + ((lane >> 4) << 3)]);
                    #pragma unroll
                    for (int nc = 0; nc < 2; ++nc) {
                        if (kh == 0) {
                            mma_bf16(accg[mt][nc], af, bg[nc].x, bg[nc].y);
                            mma_bf16(accu[mt][nc], af, bu[nc].x, bu[nc].y);
                        } else {
                            mma_bf16(accg[mt][nc], af, bg[nc].z, bg[nc].w);
                            mma_bf16(accu[mt][nc], af, bu[nc].z, bu[nc].w);
                        }
                    }
                }
            }
        }
        __syncthreads();
    }

    // epilogue: a = silu(gate) * up -> fp16 g_act
    const size_t abase = ((size_t)e*TT + m0) * II + n0;
    #pragma unroll
    for (int mt = 0; mt < 4; ++mt)
        #pragma unroll
        for (int nc = 0; nc < 2; ++nc)
            #pragma unroll
            for (int rp = 0; rp < 2; ++rp) {
                int row = mt*16 + (lane >> 2) + rp*8;
                int col = warp*16 + nc*8 + ((lane & 3) << 1);
                float g0 = accg[mt][nc][rp*2+0], g1 = accg[mt][nc][rp*2+1];
                float u0 = accu[mt][nc][rp*2+0], u1 = accu[mt][nc][rp*2+1];
                float a0 = (g0 / (1.f + __expf(-g0))) * u0;
                float a1 = (g1 / (1.f + __expf(-g1))) * u1;
                *(__half2*)(g_act + abase + (size_t)row*II + col) = __floats2half2_rn(a0, a1);
            }
}

// ---------------- kernel 5: GEMM2 (a @ W2^T), warp-n-strips, cp.async A, atomicAdd ----------------
// K chunked by 64 (12 chunks)
__global__ __launch_bounds__(128, 4) void k_gemm2(const int* __restrict__ w2,
                                                  const int* __restrict__ w2s,
                                                  float* __restrict__ out) {
    const int e = blockIdx.z;
    const int cnt = g_cnt[e];
    const int m0 = blockIdx.x * 64;
    if (m0 >= cnt) return;
    const int n0 = blockIdx.y * 64;   // [0, 2048)

    __shared__ __align__(16) __half As[2][64][72];
    __shared__ uint32_t Bp[2][64][12];
    __shared__ int s_tok[64];

    const int tid = threadIdx.x;
    const int lane = tid & 31, warp = tid >> 5;
    const int q = lane & 3, g4 = lane >> 2;
    const int rbase = tid >> 3, seg = tid & 7;

    if (tid < 64) {
        int r = m0 + tid;
        s_tok[tid] = (r < cnt) ? g_tok[e*TT + r] : -1;
    }
    __syncthreads();

    const __half* arow = g_act + ((size_t)e*TT + m0) * II;
    const int* sptr = (tid < 64) ? (w2s + (size_t)(e*DD + n0 + tid) * (II/32)) : 0;

    float acc[4][2][4];
    #pragma unroll
    for (int a = 0; a < 4; a++)
        #pragma unroll
        for (int b = 0; b < 2; b++)
            #pragma unroll
            for (int c = 0; c < 4; c++) acc[a][b][c] = 0.f;

    // ---- prefetch chunk 0 ----
    uint32_t bw[4];
    uint2 s2w = make_uint2(0, 0);
    #pragma unroll
    for (int i = 0; i < 4; ++i)
        cpa16(&As[0][rbase + 16*i][seg*8], arow + (size_t)(rbase + 16*i)*II + seg*8, 16);
    CP_COMMIT();
    #pragma unroll
    for (int i = 0; i < 4; ++i) {
        int rowg = e*DD + n0 + rbase + 16*i;
        bw[i] = gb0(*((const uint4*)(w2 + (size_t)rowg * (II/2)) + seg));
    }
    if (tid < 64) {
        int2 sf = *(const int2*)(sptr);
        s2w.x = (uint32_t)((sf.x - 112) << 10) * 0x10001u;
        s2w.y = (uint32_t)((sf.y - 112) << 10) * 0x10001u;
    }

    for (int c = 0; c < II/64; ++c) {
        const int buf = c & 1;
        CP_WAIT0();
        #pragma unroll
        for (int i = 0; i < 4; ++i) Bp[buf][rbase + 16*i][seg] = bw[i];
        if (tid < 64) {
            Bp[buf][tid][8] = s2w.x;
            Bp[buf][tid][9] = s2w.y;
        }
        __syncthreads();

        if (c + 1 < II/64) {
            #pragma unroll
            for (int i = 0; i < 4; ++i)
                cpa16(&As[buf^1][rbase + 16*i][seg*8],
                      arow + (size_t)(rbase + 16*i)*II + (c+1)*64 + seg*8, 16);
            CP_COMMIT();
            #pragma unroll
            for (int i = 0; i < 4; ++i) {
                int rowg = e*DD + n0 + rbase + 16*i;
                bw[i] = gb0(*((const uint4*)(w2 + (size_t)rowg * (II/2)) + (c+1)*8 + seg));
            }
            if (tid < 64) {
                int2 sf = *(const int2*)(sptr + 2*(c+1));
                s2w.x = (uint32_t)((sf.x - 112) << 10) * 0x10001u;
                s2w.y = (uint32_t)((sf.y - 112) << 10) * 0x10001u;
            }
        }

        #pragma unroll
        for (int kb = 0; kb < 2; ++kb) {
            uint4 bb[2];
            #pragma unroll
            for (int nc = 0; nc < 2; ++nc) {
                const int rowB = warp*16 + nc*8 + g4;
                uint4 wb = *(uint4*)&Bp[buf][rowB][4*kb];
                uint32_t sb = Bp[buf][rowB][8 + kb];
                bb[nc] = dq8p_fp16(tb(wb.x, wb.y, wb.z, wb.w, q), sb);
            }
            #pragma unroll
            for (int kh = 0; kh < 2; ++kh) {
                #pragma unroll
                for (int mt = 0; mt < 4; ++mt) {
                    uint32_t af[4];
                    ldm_x4(af, &As[buf][mt*16 + (lane & 15)][kb*32 + kh*16 + ((lane >> 4) << 3)]);
                    #pragma unroll
                    for (int nc = 0; nc < 2; ++nc) {
                        if (kh == 0) mma_f16(acc[mt][nc], af, bb[nc].x, bb[nc].y);
                        else         mma_f16(acc[mt][nc], af, bb[nc].z, bb[nc].w);
                    }
                }
            }
        }
        __syncthreads();
    }

    #pragma unroll
    for (int mt = 0; mt < 4; ++mt)
        #pragma unroll
        for (int nc = 0; nc < 2; ++nc)
            #pragma unroll
            for (int rp = 0; rp < 2; ++rp) {
                int row = mt*16 + (lane >> 2) + rp*8;
                if (m0 + row < cnt) {
                    int t = s_tok[row];
                    float cv = g_comb[t*EE + e];
                    int col = n0 + warp*16 + nc*8 + ((lane & 3) << 1);
                    atomicAdd(&out[(size_t)t*DD + col + 0], cv * acc[mt][nc][rp*2+0]);
                    atomicAdd(&out[(size_t)t*DD + col + 1], cv * acc[mt][nc][rp*2+1]);
                }
            }
}

// ---------------- launcher ----------------
extern "C" void kernel_launch(void* const* d_in, const int* in_sizes, int n_in,
                              void* d_out, int out_size) {
    const float* hs   = (const float*)d_in[0];
    const float* tw   = (const float*)d_in[1];
    const int*   tids = (const int*)d_in[2];
    const int*   w13  = (const int*)d_in[3];
    const int*   w13s = (const int*)d_in[4];
    const int*   w2   = (const int*)d_in[5];
    const int*   w2s  = (const int*)d_in[6];
    float* out = (float*)d_out;

    k_zero<<<(TT*DD + 255)/256, 256>>>(out);
    k_quant<<<(TT*DD + 255)/256, 256>>>(hs);
    k_route<<<1, TT>>>(tw, tids);
    {
        dim3 g1(TT/64, II/64, EE);      // (8, 12, 16)
        k_gemm1<<<g1, 128>>>(w13, w13s);
        dim3 g2(TT/64, DD/64, EE);      // (8, 32, 16)
        k_gemm2<<<g2, 128>>>(w2, w2s, out);
    }
    (void)in_sizes; (void)n_in; (void)out_size;
}